// round 10
// baseline (speedup 1.0000x reference)
#include <cuda_runtime.h>
#include <cuda_bf16.h>
#include <cstdint>
#include <cstddef>

// Problem dims
#define BB 4
#define TT 1024
#define EE 512
#define HH 8
#define LL 4
#define VV 32000
#define HIDN 100
#define HIDP 128
#define HD 64
#define BT (BB*TT)          // 4096
#define BHT (BB*HH*TT)      // 32768
#define QKVS 1536           // packed qkv row stride
#define ATT_PER_L ((size_t)BB*HH*TT*TT)
#define LOGITS_N ((size_t)BT*VV)

// ---------------- scratch (device globals; no allocations allowed) ----------
// Plane-packed format per row of K elems: each 32-elem chunk = 32 words laid
// out as [hi_s0 x8][hi_s1 x8][lo_s0 x8][lo_s1 x8], each group of 8 permuted so
// lane q's pairs (q, q+4) are adjacent (uint2-loadable).
__device__ float    d_x[BT*EE];                   // residual stream (fp32)
__device__ uint32_t d_h[BT*EE];                   // plane-packed LN output
__device__ uint32_t d_qkv[(size_t)BT*QKVS];       // plane-packed q,k,v
__device__ uint32_t d_y[BT*EE];                   // plane-packed attn output
__device__ uint32_t d_u[BT*HIDP];                 // plane-packed ffn hidden
__device__ float    d_S[(size_t)BB*HH*TT*TT];     // raw scores fp32
__device__ uint32_t d_vT[(size_t)BB*EE*TT];       // plane-packed V^T [b][e][s]
__device__ uint32_t d_WlmT[(size_t)VV*EE];
__device__ uint32_t d_WT[(size_t)LL*4*EE*EE];
__device__ uint32_t d_W1Tp[(size_t)LL*HIDP*EE];
__device__ uint32_t d_W2Tp[(size_t)LL*EE*HIDP];
__device__ float    d_b1p[LL*HIDP];

// ======================= helpers =============================================
#define TILE_F (128*36)
#define GEMM_SMEM (4*TILE_F*4)
#define AV_SMEM  (2*(128*36 + 64*36)*4)

__device__ __forceinline__ uint32_t smem_u32(const void* p) {
    uint32_t a;
    asm("{ .reg .u64 t; cvta.to.shared.u64 t, %1; cvt.u32.u64 %0, t; }"
        : "=r"(a) : "l"(p));
    return a;
}
__device__ __forceinline__ void cp16(uint32_t saddr, const void* g) {
    asm volatile("cp.async.cg.shared.global [%0], [%1], 16;" :: "r"(saddr), "l"(g));
}
__device__ __forceinline__ uint32_t pack2_hi(float f0, float f1) {
    uint32_t r;
    asm("cvt.rn.bf16x2.f32 %0, %1, %2;" : "=r"(r) : "f"(f1), "f"(f0));
    return r;
}
__device__ __forceinline__ uint32_t pack2_lo(float f0, float f1, uint32_t hi) {
    float h0 = __uint_as_float(hi << 16);
    float h1 = __uint_as_float(hi & 0xffff0000u);
    uint32_t r;
    asm("cvt.rn.bf16x2.f32 %0, %1, %2;" : "=r"(r) : "f"(f1 - h1), "f"(f0 - h0));
    return r;
}
// word position of the HI word for the pair whose even column is c
__device__ __forceinline__ int pos_hi(int c) {
    int jl = (c >> 1) & 15;
    int s = jl >> 3, r = jl & 7;
    int slot = (r < 4) ? 2 * r : 2 * r - 7;
    return (c & ~31) + 8 * s + slot;
}
__device__ __forceinline__ void mma_bf16(float c[4], const uint32_t a[4], const uint32_t b[2]) {
    asm volatile(
        "mma.sync.aligned.m16n8k16.row.col.f32.bf16.bf16.f32 "
        "{%0,%1,%2,%3}, {%4,%5,%6,%7}, {%8,%9}, {%0,%1,%2,%3};"
        : "+f"(c[0]), "+f"(c[1]), "+f"(c[2]), "+f"(c[3])
        : "r"(a[0]), "r"(a[1]), "r"(a[2]), "r"(a[3]), "r"(b[0]), "r"(b[1]));
}

// ======================= plane-packed bf16 mma GEMM (3-term) =================
template <bool BIAS, bool RES, bool RELU, bool SWAPG, bool PACKOUT>
__global__ void __launch_bounds__(256, 2)
mma_gemm(const uint32_t* __restrict__ A, const uint32_t* __restrict__ BT_,
         const float* __restrict__ bias, const float* __restrict__ res,
         float* __restrict__ C, int M, int N, int K) {
    extern __shared__ float smem_f[];
    uint32_t* As = (uint32_t*)smem_f;
    uint32_t* Bs = (uint32_t*)smem_f + 2*TILE_F;

    const int tid = threadIdx.x;
    const int wid = tid >> 5;
    const int lane = tid & 31;
    const int g = lane >> 2, q = lane & 3;
    const int wm = wid & 1, wn = wid >> 1;

    const int row0 = (SWAPG ? blockIdx.x : blockIdx.y) * 128;
    const int col0 = (SWAPG ? blockIdx.y : blockIdx.x) * 128;
    const uint32_t* Ap = A + (size_t)row0 * K;
    const uint32_t* Bp = BT_ + (size_t)col0 * K;

    const uint32_t sA0 = smem_u32(As);
    const uint32_t sB0 = smem_u32(Bs);

    const int NK = K >> 5;

    int lrow[4], lc4[4];
    #pragma unroll
    for (int j = 0; j < 4; j++) {
        int i = tid + j * 256;
        lrow[j] = i >> 3;
        lc4[j] = i & 7;
    }

    auto load_stage = [&](int buf, int kt) {
        const int k0 = kt << 5;
        const uint32_t offA = sA0 + buf * TILE_F * 4;
        const uint32_t offB = sB0 + buf * TILE_F * 4;
        #pragma unroll
        for (int j = 0; j < 4; j++) {
            uint32_t so = (uint32_t)(lrow[j] * 36 + lc4[j] * 4) * 4;
            cp16(offA + so, Ap + (size_t)lrow[j] * K + k0 + lc4[j] * 4);
            cp16(offB + so, Bp + (size_t)lrow[j] * K + k0 + lc4[j] * 4);
        }
        asm volatile("cp.async.commit_group;");
    };

    float acc[4][4][4];
    #pragma unroll
    for (int i = 0; i < 4; i++)
        #pragma unroll
        for (int j = 0; j < 4; j++)
            #pragma unroll
            for (int t = 0; t < 4; t++) acc[i][j][t] = 0.0f;

    load_stage(0, 0);

    int buf = 0;
    for (int kt = 0; kt < NK; kt++) {
        if (kt + 1 < NK) {
            load_stage(buf ^ 1, kt + 1);
            asm volatile("cp.async.wait_group 1;");
        } else {
            asm volatile("cp.async.wait_group 0;");
        }
        __syncthreads();

        const uint32_t* as = As + buf * TILE_F + (wm * 64 + g) * 36;
        const uint32_t* bs = Bs + buf * TILE_F + (wn * 32 + g) * 36;
        #pragma unroll
        for (int s = 0; s < 2; s++) {
            const int off = 8 * s + 2 * q;
            uint32_t ah[4][4], al[4][4], bh[4][2], bl[4][2];
            #pragma unroll
            for (int i = 0; i < 4; i++) {
                const uint32_t* p = as + i * 16 * 36 + off;
                uint2 wh  = *(const uint2*)(p);
                uint2 wh8 = *(const uint2*)(p + 8 * 36);
                uint2 wl  = *(const uint2*)(p + 16);
                uint2 wl8 = *(const uint2*)(p + 8 * 36 + 16);
                ah[i][0] = wh.x;  ah[i][1] = wh8.x;  ah[i][2] = wh.y;  ah[i][3] = wh8.y;
                al[i][0] = wl.x;  al[i][1] = wl8.x;  al[i][2] = wl.y;  al[i][3] = wl8.y;
            }
            #pragma unroll
            for (int j = 0; j < 4; j++) {
                const uint32_t* p = bs + j * 8 * 36 + off;
                uint2 wh = *(const uint2*)(p);
                uint2 wl = *(const uint2*)(p + 16);
                bh[j][0] = wh.x;  bh[j][1] = wh.y;
                bl[j][0] = wl.x;  bl[j][1] = wl.y;
            }
            #pragma unroll
            for (int i = 0; i < 4; i++)
                #pragma unroll
                for (int j = 0; j < 4; j++) {
                    mma_bf16(acc[i][j], ah[i], bl[j]);
                    mma_bf16(acc[i][j], al[i], bh[j]);
                    mma_bf16(acc[i][j], ah[i], bh[j]);
                }
        }
        __syncthreads();
        buf ^= 1;
    }

    const int m0 = row0 + wm * 64 + g;
    const int n0 = col0 + wn * 32 + 2 * q;
    #pragma unroll
    for (int i = 0; i < 4; i++) {
        #pragma unroll
        for (int j = 0; j < 4; j++) {
            int c = n0 + j * 8;
            float b0 = 0.f, b1 = 0.f;
            if (BIAS) { b0 = bias[c]; b1 = bias[c + 1]; }
            #pragma unroll
            for (int hh = 0; hh < 2; hh++) {
                int r = m0 + i * 16 + hh * 8;
                float v0 = acc[i][j][hh * 2 + 0] + b0;
                float v1 = acc[i][j][hh * 2 + 1] + b1;
                if (RES) {
                    const float* rp = res + (size_t)r * N + c;
                    v0 += rp[0]; v1 += rp[1];
                }
                if (RELU) { v0 = fmaxf(v0, 0.f); v1 = fmaxf(v1, 0.f); }
                if (PACKOUT) {
                    uint32_t H = pack2_hi(v0, v1);
                    uint32_t L = pack2_lo(v0, v1, H);
                    uint32_t* orow = (uint32_t*)C + (size_t)r * N;
                    int ph = pos_hi(c);
                    orow[ph] = H;
                    orow[ph + 16] = L;
                } else {
                    float2* cp = (float2*)(C + (size_t)r * N + c);
                    *cp = make_float2(v0, v1);
                }
            }
        }
    }
}

// ======================= QK^T via plane-packed bf16 mma ======================
__global__ void __launch_bounds__(256, 2)
qk_mma(const uint32_t* __restrict__ qkv, float* __restrict__ S) {
    if (blockIdx.x > blockIdx.y) return;
    extern __shared__ float smem_f[];
    uint32_t* As = (uint32_t*)smem_f;
    uint32_t* Bs = (uint32_t*)smem_f + 2*TILE_F;

    const int tid = threadIdx.x;
    const int wid = tid >> 5;
    const int lane = tid & 31;
    const int g = lane >> 2, q = lane & 3;
    const int wm = wid & 1, wn = wid >> 1;

    const int row0 = blockIdx.y * 128;
    const int col0 = blockIdx.x * 128;
    const int b = blockIdx.z >> 3, h = blockIdx.z & 7;
    const uint32_t* Ap = qkv + ((size_t)b*TT + row0) * QKVS + h*HD;
    const uint32_t* Bp = qkv + 512 + ((size_t)b*TT + col0) * QKVS + h*HD;

    const uint32_t sA0 = smem_u32(As);
    const uint32_t sB0 = smem_u32(Bs);

    int lrow[4], lc4[4];
    #pragma unroll
    for (int j = 0; j < 4; j++) {
        int i = tid + j * 256;
        lrow[j] = i >> 3;
        lc4[j] = i & 7;
    }

    auto load_stage = [&](int buf, int kt) {
        const int k0 = kt << 5;
        const uint32_t offA = sA0 + buf * TILE_F * 4;
        const uint32_t offB = sB0 + buf * TILE_F * 4;
        #pragma unroll
        for (int j = 0; j < 4; j++) {
            uint32_t so = (uint32_t)(lrow[j] * 36 + lc4[j] * 4) * 4;
            cp16(offA + so, Ap + (size_t)lrow[j] * QKVS + k0 + lc4[j] * 4);
            cp16(offB + so, Bp + (size_t)lrow[j] * QKVS + k0 + lc4[j] * 4);
        }
        asm volatile("cp.async.commit_group;");
    };

    float acc[4][4][4];
    #pragma unroll
    for (int i = 0; i < 4; i++)
        #pragma unroll
        for (int j = 0; j < 4; j++)
            #pragma unroll
            for (int t = 0; t < 4; t++) acc[i][j][t] = 0.0f;

    load_stage(0, 0);

    int buf = 0;
    for (int kt = 0; kt < 2; kt++) {
        if (kt == 0) {
            load_stage(1, 1);
            asm volatile("cp.async.wait_group 1;");
        } else {
            asm volatile("cp.async.wait_group 0;");
        }
        __syncthreads();

        const uint32_t* as = As + buf * TILE_F + (wm * 64 + g) * 36;
        const uint32_t* bs = Bs + buf * TILE_F + (wn * 32 + g) * 36;
        #pragma unroll
        for (int s = 0; s < 2; s++) {
            const int off = 8 * s + 2 * q;
            uint32_t ah[4][4], al[4][4], bh[4][2], bl[4][2];
            #pragma unroll
            for (int i = 0; i < 4; i++) {
                const uint32_t* p = as + i * 16 * 36 + off;
                uint2 wh  = *(const uint2*)(p);
                uint2 wh8 = *(const uint2*)(p + 8 * 36);
                uint2 wl  = *(const uint2*)(p + 16);
                uint2 wl8 = *(const uint2*)(p + 8 * 36 + 16);
                ah[i][0] = wh.x;  ah[i][1] = wh8.x;  ah[i][2] = wh.y;  ah[i][3] = wh8.y;
                al[i][0] = wl.x;  al[i][1] = wl8.x;  al[i][2] = wl.y;  al[i][3] = wl8.y;
            }
            #pragma unroll
            for (int j = 0; j < 4; j++) {
                const uint32_t* p = bs + j * 8 * 36 + off;
                uint2 wh = *(const uint2*)(p);
                uint2 wl = *(const uint2*)(p + 16);
                bh[j][0] = wh.x;  bh[j][1] = wh.y;
                bl[j][0] = wl.x;  bl[j][1] = wl.y;
            }
            #pragma unroll
            for (int i = 0; i < 4; i++)
                #pragma unroll
                for (int j = 0; j < 4; j++) {
                    mma_bf16(acc[i][j], ah[i], bl[j]);
                    mma_bf16(acc[i][j], al[i], bh[j]);
                    mma_bf16(acc[i][j], ah[i], bh[j]);
                }
        }
        __syncthreads();
        buf ^= 1;
    }

    float* Sp = S + (size_t)blockIdx.z * TT * TT;
    const int m0 = row0 + wm * 64 + g;
    const int n0 = col0 + wn * 32 + 2 * q;
    #pragma unroll
    for (int i = 0; i < 4; i++)
        #pragma unroll
        for (int j = 0; j < 4; j++) {
            int c = n0 + j * 8;
            #pragma unroll
            for (int hh = 0; hh < 2; hh++) {
                int r = m0 + i * 16 + hh * 8;
                float2* cp = (float2*)(Sp + (size_t)r * TT + c);
                *cp = make_float2(acc[i][j][hh*2+0] * 0.125f, acc[i][j][hh*2+1] * 0.125f);
            }
        }
}

// ======================= P @ V via bf16 mma ==================================
#define AV_AF (128*36)
#define AV_BF (64*36)
__global__ void __launch_bounds__(256, 2)
av_mma(const float* __restrict__ P, const uint32_t* __restrict__ vT,
       uint32_t* __restrict__ y) {
    extern __shared__ float smem_f[];
    float* As = smem_f;
    uint32_t* Bs = (uint32_t*)smem_f + 2*AV_AF;

    const int tid = threadIdx.x;
    const int wid = tid >> 5;
    const int lane = tid & 31;
    const int g = lane >> 2, q = lane & 3;
    const int wm = wid & 3, wn = wid >> 2;

    const int row0 = blockIdx.x * 128;
    const int b = blockIdx.z >> 3, h = blockIdx.z & 7;
    const float* Ap = P + (size_t)blockIdx.z * TT * TT + (size_t)row0 * TT;
    const uint32_t* Bp = vT + ((size_t)b*EE + h*HD) * TT;

    const uint32_t sA0 = smem_u32(As);
    const uint32_t sB0 = smem_u32(Bs);

    const int NK = (row0 >> 5) + 4;

    int arow[4], ac4[4], brow[2], bc4[2];
    #pragma unroll
    for (int j = 0; j < 4; j++) {
        int i = tid + j * 256;
        arow[j] = i >> 3; ac4[j] = i & 7;
    }
    #pragma unroll
    for (int j = 0; j < 2; j++) {
        int i = tid + j * 256;
        brow[j] = i >> 3; bc4[j] = i & 7;
    }

    auto load_stage = [&](int buf, int kt) {
        const int k0 = kt << 5;
        const uint32_t offA = sA0 + buf * AV_AF * 4;
        const uint32_t offB = sB0 + buf * AV_BF * 4;
        #pragma unroll
        for (int j = 0; j < 4; j++) {
            uint32_t so = (uint32_t)(arow[j] * 36 + ac4[j] * 4) * 4;
            cp16(offA + so, Ap + (size_t)arow[j] * TT + k0 + ac4[j] * 4);
        }
        #pragma unroll
        for (int j = 0; j < 2; j++) {
            uint32_t so = (uint32_t)(brow[j] * 36 + bc4[j] * 4) * 4;
            cp16(offB + so, Bp + (size_t)brow[j] * TT + k0 + bc4[j] * 4);
        }
        asm volatile("cp.async.commit_group;");
    };

    float acc[2][4][4];
    #pragma unroll
    for (int i = 0; i < 2; i++)
        #pragma unroll
        for (int j = 0; j < 4; j++)
            #pragma unroll
            for (int t = 0; t < 4; t++) acc[i][j][t] = 0.0f;

    load_stage(0, 0);

    int buf = 0;
    for (int kt = 0; kt < NK; kt++) {
        if (kt + 1 < NK) {
            load_stage(buf ^ 1, kt + 1);
            asm volatile("cp.async.wait_group 1;");
        } else {
            asm volatile("cp.async.wait_group 0;");
        }
        __syncthreads();

        const float* as = As + buf * AV_AF + (wm * 32 + g) * 36 + 2 * q;
        const uint32_t* bs = Bs + buf * AV_BF + (wn * 32 + g) * 36;
        #pragma unroll
        for (int s = 0; s < 2; s++) {
            const int k0f = s * 16;           // fp32 A offset
            const int off = 8 * s + 2 * q;    // plane B offset
            uint32_t ah[2][4], al[2][4], bh[4][2], bl[4][2];
            #pragma unroll
            for (int i = 0; i < 2; i++) {
                const float* p = as + i * 16 * 36 + k0f;
                float2 x0 = *(const float2*)(p);
                float2 x1 = *(const float2*)(p + 8 * 36);
                float2 x2 = *(const float2*)(p + 8);
                float2 x3 = *(const float2*)(p + 8 * 36 + 8);
                ah[i][0] = pack2_hi(x0.x, x0.y); al[i][0] = pack2_lo(x0.x, x0.y, ah[i][0]);
                ah[i][1] = pack2_hi(x1.x, x1.y); al[i][1] = pack2_lo(x1.x, x1.y, ah[i][1]);
                ah[i][2] = pack2_hi(x2.x, x2.y); al[i][2] = pack2_lo(x2.x, x2.y, ah[i][2]);
                ah[i][3] = pack2_hi(x3.x, x3.y); al[i][3] = pack2_lo(x3.x, x3.y, ah[i][3]);
            }
            #pragma unroll
            for (int j = 0; j < 4; j++) {
                const uint32_t* p = bs + j * 8 * 36 + off;
                uint2 wh = *(const uint2*)(p);
                uint2 wl = *(const uint2*)(p + 16);
                bh[j][0] = wh.x;  bh[j][1] = wh.y;
                bl[j][0] = wl.x;  bl[j][1] = wl.y;
            }
            #pragma unroll
            for (int i = 0; i < 2; i++)
                #pragma unroll
                for (int j = 0; j < 4; j++) {
                    mma_bf16(acc[i][j], ah[i], bl[j]);
                    mma_bf16(acc[i][j], al[i], bh[j]);
                    mma_bf16(acc[i][j], ah[i], bh[j]);
                }
        }
        __syncthreads();
        buf ^= 1;
    }

    const int m0 = row0 + wm * 32 + g;
    const int n0 = wn * 32 + 2 * q;
    #pragma unroll
    for (int i = 0; i < 2; i++)
        #pragma unroll
        for (int j = 0; j < 4; j++) {
            int c = n0 + j * 8;
            #pragma unroll
            for (int hh = 0; hh < 2; hh++) {
                int r = m0 + i * 16 + hh * 8;
                float v0 = acc[i][j][hh*2+0], v1 = acc[i][j][hh*2+1];
                uint32_t H = pack2_hi(v0, v1);
                uint32_t L = pack2_lo(v0, v1, H);
                uint32_t* orow = y + ((size_t)b*TT + r) * EE;
                int ph = pos_hi(h*HD + c);
                orow[ph] = H;
                orow[ph + 16] = L;
            }
        }
}

// ---------------- transpose + plane-pack: W[K,N] -> WT[N,K] ------------------
__global__ void transpose_pack_kernel(const float* __restrict__ W, uint32_t* __restrict__ WT,
                                      int K, int N) {
    __shared__ float t[32][33];
    int n0 = blockIdx.x * 32, k0 = blockIdx.y * 32;
    int x = threadIdx.x, y = threadIdx.y;
    #pragma unroll
    for (int j = 0; j < 32; j += 8)
        t[y + j][x] = W[(size_t)(k0 + y + j) * N + n0 + x];
    __syncthreads();
    #pragma unroll
    for (int j = 0; j < 32; j += 8) {
        float f = t[x][y + j];
        int n = n0 + y + j, k = k0 + x;
        uint32_t Hw = pack2_hi(f, 0.f);
        uint16_t h16 = (uint16_t)Hw;
        float hf = __uint_as_float((uint32_t)h16 << 16);
        uint16_t l16 = (uint16_t)pack2_hi(f - hf, 0.f);
        int ph = pos_hi(k & ~1), par = k & 1;
        uint16_t* row16 = (uint16_t*)(WT + (size_t)n * K);
        row16[ph * 2 + par] = h16;
        row16[(ph + 16) * 2 + par] = l16;
    }
}

// padded transpose + plane-pack (zero fill)
__global__ void pad_transpose_pack_kernel(const float* __restrict__ W, uint32_t* __restrict__ WT,
                                          int K, int N, int Kp, int Np) {
    __shared__ float t[32][33];
    int n0 = blockIdx.x * 32, k0 = blockIdx.y * 32;
    int x = threadIdx.x, y = threadIdx.y;
    #pragma unroll
    for (int j = 0; j < 32; j += 8) {
        int kk = k0 + y + j, nn = n0 + x;
        t[y + j][x] = (kk < K && nn < N) ? W[(size_t)kk * N + nn] : 0.0f;
    }
    __syncthreads();
    #pragma unroll
    for (int j = 0; j < 32; j += 8) {
        float f = t[x][y + j];
        int n = n0 + y + j, k = k0 + x;
        uint32_t Hw = pack2_hi(f, 0.f);
        uint16_t h16 = (uint16_t)Hw;
        float hf = __uint_as_float((uint32_t)h16 << 16);
        uint16_t l16 = (uint16_t)pack2_hi(f - hf, 0.f);
        int ph = pos_hi(k & ~1), par = k & 1;
        uint16_t* row16 = (uint16_t*)(WT + (size_t)n * Kp);
        row16[ph * 2 + par] = h16;
        row16[(ph + 16) * 2 + par] = l16;
    }
}

__global__ void pad_b1_kernel(const float* __restrict__ b1, float* __restrict__ b1p) {
    int l = blockIdx.x, tid = threadIdx.x;
    b1p[l * HIDP + tid] = (tid < HIDN) ? b1[l * HIDN + tid] : 0.0f;
}

// transpose plane-packed V -> vT[b][e][s] (repack along s)
__global__ void vtrans_kernel(const uint32_t* __restrict__ qkv, uint32_t* __restrict__ vT) {
    __shared__ uint32_t t[32][33];     // t[s_local][e_local] = hi16 | lo16<<16
    int s0 = blockIdx.x * 32, e0 = blockIdx.y * 32, b = blockIdx.z;
    int x = threadIdx.x, y = threadIdx.y;
    #pragma unroll
    for (int j = 0; j < 32; j += 8) {
        int s = s0 + y + j;
        int col = 1024 + e0 + x;
        const uint16_t* r16 = (const uint16_t*)(qkv + ((size_t)b*TT + s) * QKVS);
        int ph = pos_hi(col & ~1), par = col & 1;
        uint32_t h16 = r16[ph * 2 + par];
        uint32_t l16 = r16[(ph + 16) * 2 + par];
        t[y + j][x] = h16 | (l16 << 16);
    }
    __syncthreads();
    #pragma unroll
    for (int j = 0; j < 32; j += 8) {
        int e = e0 + y + j, s = s0 + x;
        uint32_t w = t[x][y + j];
        uint16_t* w16 = (uint16_t*)(vT + ((size_t)b*EE + e) * TT);
        int ph = pos_hi(s & ~1), par = s & 1;
        w16[ph * 2 + par] = (uint16_t)(w & 0xffffu);
        w16[(ph + 16) * 2 + par] = (uint16_t)(w >> 16);
    }
}

// ---------------- embed ------------------------------------------------------
__global__ void embed_kernel(const int* __restrict__ idx,
                             const float* __restrict__ tok,
                             const float* __restrict__ pos,
                             float* __restrict__ x) {
    int row = blockIdx.x;
    int t = row & (TT - 1);
    int token = idx[row];
    const float4* tp = (const float4*)(tok + (size_t)token * EE);
    const float4* pp = (const float4*)(pos + (size_t)t * EE);
    float4* xp = (float4*)(x + (size_t)row * EE);
    int c = threadIdx.x;
    float4 a = tp[c], b = pp[c];
    xp[c] = make_float4(a.x + b.x, a.y + b.y, a.z + b.z, a.w + b.w);
}

// ---------------- layernorm -> plane-packed output ---------------------------
__global__ void ln_kernel(const float* __restrict__ x, uint32_t* __restrict__ out,
                          const float* __restrict__ g, const float* __restrict__ b) {
    int row = blockIdx.x;
    int tid = threadIdx.x;
    const float4* xp = (const float4*)(x + (size_t)row * EE);
    float4 v = xp[tid];
    float s = v.x + v.y + v.z + v.w;
    __shared__ float red[4];
    for (int o = 16; o; o >>= 1) s += __shfl_xor_sync(~0u, s, o);
    if ((tid & 31) == 0) red[tid >> 5] = s;
    __syncthreads();
    float mean = (red[0] + red[1] + red[2] + red[3]) / (float)EE;
    float dx = v.x - mean, dy = v.y - mean, dz = v.z - mean, dw = v.w - mean;
    float ss = dx*dx + dy*dy + dz*dz + dw*dw;
    __syncthreads();
    for (int o = 16; o; o >>= 1) ss += __shfl_xor_sync(~0u, ss, o);
    if ((tid & 31) == 0) red[tid >> 5] = ss;
    __syncthreads();
    float var = (red[0] + red[1] + red[2] + red[3]) / (float)EE;
    float inv = 1.0f / sqrtf(var + 1e-5f);
    const float4* gp = (const float4*)g;
    const float4* bp = (const float4*)b;
    float4 gg = gp[tid], bb = bp[tid];
    float o0 = dx*inv*gg.x + bb.x, o1 = dy*inv*gg.y + bb.y;
    float o2 = dz*inv*gg.z + bb.z, o3 = dw*inv*gg.w + bb.w;
    uint32_t* orow = out + (size_t)row * EE;
    int c0 = 4 * tid;
    uint32_t H0 = pack2_hi(o0, o1), L0 = pack2_lo(o0, o1, H0);
    uint32_t H1 = pack2_hi(o2, o3), L1 = pack2_lo(o2, o3, H1);
    int p0 = pos_hi(c0), p1 = pos_hi(c0 + 2);
    orow[p0] = H0; orow[p0 + 16] = L0;
    orow[p1] = H1; orow[p1 + 16] = L1;
}

// ---------------- causal softmax row -> writes attn map into d_out ----------
__global__ void softmax_kernel(const float* __restrict__ S, float* __restrict__ out) {
    int row = blockIdx.x;
    int t = row & (TT - 1);
    const float* sp = S + (size_t)row * TT;
    float* op = out + (size_t)row * TT;
    int tid = threadIdx.x;
    float vals[4];
    float m = -1e30f;
    #pragma unroll
    for (int i = 0; i < 4; i++) {
        int s = tid + i * 256;
        vals[i] = (s <= t) ? sp[s] : -1e30f;
        m = fmaxf(m, vals[i]);
    }
    __shared__ float red[8];
    for (int o = 16; o; o >>= 1) m = fmaxf(m, __shfl_xor_sync(~0u, m, o));
    if ((tid & 31) == 0) red[tid >> 5] = m;
    __syncthreads();
    m = red[0];
    #pragma unroll
    for (int i = 1; i < 8; i++) m = fmaxf(m, red[i]);
    float e[4];
    float ssum = 0.0f;
    #pragma unroll
    for (int i = 0; i < 4; i++) {
        int s = tid + i * 256;
        e[i] = (s <= t) ? expf(vals[i] - m) : 0.0f;
        ssum += e[i];
    }
    __syncthreads();
    for (int o = 16; o; o >>= 1) ssum += __shfl_xor_sync(~0u, ssum, o);
    if ((tid & 31) == 0) red[tid >> 5] = ssum;
    __syncthreads();
    float tot = 0.0f;
    #pragma unroll
    for (int i = 0; i < 8; i++) tot += red[i];
    float inv = 1.0f / tot;
    #pragma unroll
    for (int i = 0; i < 4; i++) {
        int s = tid + i * 256;
        op[s] = e[i] * inv;
    }
}

// ---------------- host orchestration ----------------------------------------
extern "C" void kernel_launch(void* const* d_in, const int* in_sizes, int n_in,
                              void* d_out, int out_size) {
    (void)in_sizes; (void)n_in; (void)out_size;
    const int*   idx     = (const int*)  d_in[0];
    const float* tok_emb = (const float*)d_in[1];
    const float* pos_emb = (const float*)d_in[2];
    const float* ln1_g   = (const float*)d_in[3];
    const float* ln1_b   = (const float*)d_in[4];
    const float* Wq      = (const float*)d_in[5];
    const float* Wk      = (const float*)d_in[6];
    const float* Wv      = (const float*)d_in[7];
    const float* Wo      = (const float*)d_in[8];
    const float* bo      = (const float*)d_in[9];
    const float* ln2_g   = (const float*)d_in[10];
    const float* ln2_b   = (const float*)d_in[11];
    const float* W1      = (const float*)d_in[12];
    const float* b1      = (const float*)d_in[13];
    const float* W2      = (const float*)d_in[14];
    const float* b2      = (const float*)d_in[15];
    const float* lnf_g   = (const float*)d_in[16];
    const float* lnf_b   = (const float*)d_in[17];
    const float* Wlm     = (const float*)d_in[18];

    float* out    = (float*)d_out;
    float* logits = out;
    float* attn   = out + LOGITS_N;

    float *gx, *gS, *gb1p;
    uint32_t *gh, *gqkv, *gy, *gu, *gvT, *gWlmT, *gWT, *gW1Tp, *gW2Tp;
    cudaGetSymbolAddress((void**)&gx, d_x);
    cudaGetSymbolAddress((void**)&gh, d_h);
    cudaGetSymbolAddress((void**)&gqkv, d_qkv);
    cudaGetSymbolAddress((void**)&gy, d_y);
    cudaGetSymbolAddress((void**)&gu, d_u);
    cudaGetSymbolAddress((void**)&gS, d_S);
    cudaGetSymbolAddress((void**)&gvT, d_vT);
    cudaGetSymbolAddress((void**)&gWlmT, d_WlmT);
    cudaGetSymbolAddress((void**)&gWT, d_WT);
    cudaGetSymbolAddress((void**)&gW1Tp, d_W1Tp);
    cudaGetSymbolAddress((void**)&gW2Tp, d_W2Tp);
    cudaGetSymbolAddress((void**)&gb1p, d_b1p);

    cudaFuncSetAttribute(mma_gemm<false,false,false,false,true>,
                         cudaFuncAttributeMaxDynamicSharedMemorySize, GEMM_SMEM);
    cudaFuncSetAttribute(mma_gemm<true,true,false,false,false>,
                         cudaFuncAttributeMaxDynamicSharedMemorySize, GEMM_SMEM);
    cudaFuncSetAttribute(mma_gemm<true,false,true,false,true>,
                         cudaFuncAttributeMaxDynamicSharedMemorySize, GEMM_SMEM);
    cudaFuncSetAttribute(mma_gemm<false,false,false,true,false>,
                         cudaFuncAttributeMaxDynamicSharedMemorySize, GEMM_SMEM);
    cudaFuncSetAttribute(qk_mma, cudaFuncAttributeMaxDynamicSharedMemorySize, GEMM_SMEM);
    cudaFuncSetAttribute(av_mma, cudaFuncAttributeMaxDynamicSharedMemorySize, AV_SMEM);

    // Weight prep: transpose + plane-pack
    {
        dim3 tb(32, 8);
        for (int l = 0; l < LL; l++) {
            uint32_t* base = gWT + (size_t)l * 4 * EE * EE;
            transpose_pack_kernel<<<dim3(EE/32, EE/32), tb>>>(Wq + (size_t)l*EE*EE, base,                 EE, EE);
            transpose_pack_kernel<<<dim3(EE/32, EE/32), tb>>>(Wk + (size_t)l*EE*EE, base + (size_t)512*EE, EE, EE);
            transpose_pack_kernel<<<dim3(EE/32, EE/32), tb>>>(Wv + (size_t)l*EE*EE, base + (size_t)1024*EE, EE, EE);
            transpose_pack_kernel<<<dim3(EE/32, EE/32), tb>>>(Wo + (size_t)l*EE*EE, base + (size_t)1536*EE, EE, EE);
            pad_transpose_pack_kernel<<<dim3(HIDP/32, EE/32), tb>>>(
                W1 + (size_t)l*EE*HIDN, gW1Tp + (size_t)l*HIDP*EE, EE, HIDN, EE, HIDP);
            pad_transpose_pack_kernel<<<dim3(EE/32, HIDP/32), tb>>>(
                W2 + (size_t)l*HIDN*EE, gW2Tp + (size_t)l*EE*HIDP, HIDN, EE, HIDP, EE);
        }
        pad_b1_kernel<<<LL, HIDP>>>(b1, gb1p);
        transpose_pack_kernel<<<dim3(VV/32, EE/32), tb>>>(Wlm, gWlmT, EE, VV);
    }

    embed_kernel<<<BT, 128>>>(idx, tok_emb, pos_emb, gx);

    for (int l = 0; l < LL; l++) {
        uint32_t* base = gWT + (size_t)l * 4 * EE * EE;
        const uint32_t* qkvT = base;
        const uint32_t* woT  = base + (size_t)1536*EE;
        float* attn_l = attn + (size_t)l * ATT_PER_L;

        ln_kernel<<<BT, 128>>>(gx, gh, ln1_g + l*EE, ln1_b + l*EE);

        mma_gemm<false,false,false,false,true><<<dim3(QKVS/128, BT/128), 256, GEMM_SMEM>>>(
            gh, qkvT, nullptr, nullptr, (float*)gqkv, BT, QKVS, EE);

        qk_mma<<<dim3(8, 8, BB*HH), 256, GEMM_SMEM>>>(gqkv, gS);
        softmax_kernel<<<BHT, 256>>>(gS, attn_l);
        vtrans_kernel<<<dim3(TT/32, EE/32, BB), dim3(32, 8)>>>(gqkv, gvT);
        av_mma<<<dim3(8, 1, BB*HH), 256, AV_SMEM>>>(attn_l, gvT, gy);

        mma_gemm<true,true,false,false,false><<<dim3(EE/128, BT/128), 256, GEMM_SMEM>>>(
            gy, woT, bo + l*EE, gx, gx, BT, EE, EE);

        ln_kernel<<<BT, 128>>>(gx, gh, ln2_g + l*EE, ln2_b + l*EE);

        mma_gemm<true,false,true,false,true><<<dim3(HIDP/128, BT/128), 256, GEMM_SMEM>>>(
            gh, gW1Tp + (size_t)l*HIDP*EE, gb1p + l*HIDP, nullptr, (float*)gu, BT, HIDP, EE);
        mma_gemm<true,true,false,false,false><<<dim3(EE/128, BT/128), 256, GEMM_SMEM>>>(
            gu, gW2Tp + (size_t)l*EE*HIDP, b2 + l*EE, gx, gx, BT, EE, HIDP);
    }

    ln_kernel<<<BT, 128>>>(gx, gh, lnf_g, lnf_b);
    mma_gemm<false,false,false,true,false><<<dim3(BT/128, VV/128), 256, GEMM_SMEM>>>(
        gh, gWlmT, nullptr, nullptr, logits, BT, VV, EE);
}

// round 11
// speedup vs baseline: 1.0286x; 1.0286x over previous
#include <cuda_runtime.h>
#include <cuda_bf16.h>
#include <cstdint>
#include <cstddef>

// Problem dims
#define BB 4
#define TT 1024
#define EE 512
#define HH 8
#define LL 4
#define VV 32000
#define HIDN 100
#define HIDP 128
#define HD 64
#define BT (BB*TT)          // 4096
#define BHT (BB*HH*TT)      // 32768
#define QKVS 1536           // packed qkv row stride
#define ATT_PER_L ((size_t)BB*HH*TT*TT)
#define LOGITS_N ((size_t)BT*VV)

// ---------------- scratch (device globals; no allocations allowed) ----------
// Packed format: uint32 = bf16_hi(f) | bf16_lo(f - hi) << 16
__device__ float    d_x[BT*EE];                   // residual stream (fp32)
__device__ uint32_t d_h[BT*EE];                   // packed LN output
__device__ uint32_t d_qkv[(size_t)BT*QKVS];       // packed q,k,v
__device__ uint32_t d_y[BT*EE];                   // packed attn output
__device__ uint32_t d_u[BT*HIDP];                 // packed ffn hidden
__device__ float    d_S[(size_t)BB*HH*TT*TT];     // raw scores fp32, 128 MB
__device__ uint32_t d_vT[(size_t)BB*EE*TT];       // packed V^T [b][e][s]
__device__ uint32_t d_WlmT[(size_t)VV*EE];        // packed Wlm^T [V,E]
__device__ uint32_t d_WT[(size_t)LL*4*EE*EE];     // packed per-layer qkvT+woT
__device__ uint32_t d_W1Tp[(size_t)LL*HIDP*EE];   // packed padded W1^T
__device__ uint32_t d_W2Tp[(size_t)LL*EE*HIDP];   // packed padded W2^T
__device__ float    d_b1p[LL*HIDP];

// ======================= helpers =============================================
#define TILE_F (128*36)           // elems per smem tile (padded rows)
#define GEMM_SMEM (4*TILE_F*4)
#define AV_SMEM  (2*(128*36 + 64*36)*4)

__device__ __forceinline__ uint32_t smem_u32(const void* p) {
    uint32_t a;
    asm("{ .reg .u64 t; cvta.to.shared.u64 t, %1; cvt.u32.u64 %0, t; }"
        : "=r"(a) : "l"(p));
    return a;
}
__device__ __forceinline__ void cp16(uint32_t saddr, const void* g) {
    asm volatile("cp.async.cg.shared.global [%0], [%1], 16;" :: "r"(saddr), "l"(g));
}
__device__ __forceinline__ uint32_t pack2_hi(float f0, float f1) {
    uint32_t r;
    asm("cvt.rn.bf16x2.f32 %0, %1, %2;" : "=r"(r) : "f"(f1), "f"(f0));
    return r;
}
__device__ __forceinline__ uint32_t pack2_lo(float f0, float f1, uint32_t hi) {
    float h0 = __uint_as_float(hi << 16);
    float h1 = __uint_as_float(hi & 0xffff0000u);
    uint32_t r;
    asm("cvt.rn.bf16x2.f32 %0, %1, %2;" : "=r"(r) : "f"(f1 - h1), "f"(f0 - h0));
    return r;
}
// pack one fp32 into hi|lo<<16
__device__ __forceinline__ uint32_t packelem(float f) {
    uint32_t H = pack2_hi(f, 0.0f);
    float hf = __uint_as_float(H << 16);
    uint32_t L = pack2_hi(f - hf, 0.0f);
    return (H & 0xffffu) | (L << 16);
}
// pack a consecutive pair (n, n+1) -> two packed words
__device__ __forceinline__ uint2 packpair(float f0, float f1) {
    uint32_t H = pack2_hi(f0, f1);
    uint32_t L = pack2_lo(f0, f1, H);
    return make_uint2(__byte_perm(H, L, 0x5410), __byte_perm(H, L, 0x7632));
}
// unpack two packed words (adjacent k) into bf16x2 hi and lo fragments
__device__ __forceinline__ void unpk(uint2 w, uint32_t& hi, uint32_t& lo) {
    hi = __byte_perm(w.x, w.y, 0x5410);
    lo = __byte_perm(w.x, w.y, 0x7632);
}
__device__ __forceinline__ void mma_bf16(float c[4], const uint32_t a[4], const uint32_t b[2]) {
    asm volatile(
        "mma.sync.aligned.m16n8k16.row.col.f32.bf16.bf16.f32 "
        "{%0,%1,%2,%3}, {%4,%5,%6,%7}, {%8,%9}, {%0,%1,%2,%3};"
        : "+f"(c[0]), "+f"(c[1]), "+f"(c[2]), "+f"(c[3])
        : "r"(a[0]), "r"(a[1]), "r"(a[2]), "r"(a[3]), "r"(b[0]), "r"(b[1]));
}

// ======================= packed bf16 mma GEMM (3-term) =======================
// C[M,N] = A[M,K] @ W[K,N]; A and BT_ are PACKED uint32, BT_ is [N,K].
// Single-barrier double-buffered mainloop.
template <bool BIAS, bool RES, bool RELU, bool SWAPG, bool PACKOUT>
__global__ void __launch_bounds__(256, 2)
mma_gemm(const uint32_t* __restrict__ A, const uint32_t* __restrict__ BT_,
         const float* __restrict__ bias, const float* __restrict__ res,
         float* __restrict__ C, int M, int N, int K) {
    extern __shared__ float smem_f[];
    uint32_t* As = (uint32_t*)smem_f;
    uint32_t* Bs = (uint32_t*)smem_f + 2*TILE_F;

    const int tid = threadIdx.x;
    const int wid = tid >> 5;
    const int lane = tid & 31;
    const int g = lane >> 2, q = lane & 3;
    const int wm = wid & 1, wn = wid >> 1;

    const int row0 = (SWAPG ? blockIdx.x : blockIdx.y) * 128;
    const int col0 = (SWAPG ? blockIdx.y : blockIdx.x) * 128;
    const uint32_t* Ap = A + (size_t)row0 * K;
    const uint32_t* Bp = BT_ + (size_t)col0 * K;

    const uint32_t sA0 = smem_u32(As);
    const uint32_t sB0 = smem_u32(Bs);

    const int NK = K >> 5;

    int lrow[4], lc4[4];
    #pragma unroll
    for (int j = 0; j < 4; j++) {
        int i = tid + j * 256;
        lrow[j] = i >> 3;
        lc4[j] = i & 7;
    }

    auto load_stage = [&](int buf, int kt) {
        const int k0 = kt << 5;
        const uint32_t offA = sA0 + buf * TILE_F * 4;
        const uint32_t offB = sB0 + buf * TILE_F * 4;
        #pragma unroll
        for (int j = 0; j < 4; j++) {
            uint32_t so = (uint32_t)(lrow[j] * 36 + lc4[j] * 4) * 4;
            cp16(offA + so, Ap + (size_t)lrow[j] * K + k0 + lc4[j] * 4);
            cp16(offB + so, Bp + (size_t)lrow[j] * K + k0 + lc4[j] * 4);
        }
        asm volatile("cp.async.commit_group;");
    };

    float acc[4][4][4];
    #pragma unroll
    for (int i = 0; i < 4; i++)
        #pragma unroll
        for (int j = 0; j < 4; j++)
            #pragma unroll
            for (int t = 0; t < 4; t++) acc[i][j][t] = 0.0f;

    load_stage(0, 0);

    int buf = 0;
    for (int kt = 0; kt < NK; kt++) {
        asm volatile("cp.async.wait_group 0;");
        __syncthreads();                         // buf data visible; buf^1 free
        if (kt + 1 < NK) load_stage(buf ^ 1, kt + 1);

        const uint32_t* as = As + buf * TILE_F + (wm * 64 + g) * 36 + 2 * q;
        const uint32_t* bs = Bs + buf * TILE_F + (wn * 32 + g) * 36 + 2 * q;
        #pragma unroll
        for (int s = 0; s < 2; s++) {
            const int k0 = s * 16;
            uint32_t ah[4][4], al[4][4], bh[4][2], bl[4][2];
            #pragma unroll
            for (int i = 0; i < 4; i++) {
                const uint32_t* p = as + i * 16 * 36 + k0;
                unpk(*(const uint2*)(p),              ah[i][0], al[i][0]);
                unpk(*(const uint2*)(p + 8 * 36),     ah[i][1], al[i][1]);
                unpk(*(const uint2*)(p + 8),          ah[i][2], al[i][2]);
                unpk(*(const uint2*)(p + 8 * 36 + 8), ah[i][3], al[i][3]);
            }
            #pragma unroll
            for (int j = 0; j < 4; j++) {
                const uint32_t* p = bs + j * 8 * 36 + k0;
                unpk(*(const uint2*)(p),     bh[j][0], bl[j][0]);
                unpk(*(const uint2*)(p + 8), bh[j][1], bl[j][1]);
            }
            #pragma unroll
            for (int i = 0; i < 4; i++)
                #pragma unroll
                for (int j = 0; j < 4; j++) {
                    mma_bf16(acc[i][j], ah[i], bl[j]);
                    mma_bf16(acc[i][j], al[i], bh[j]);
                    mma_bf16(acc[i][j], ah[i], bh[j]);
                }
        }
        buf ^= 1;
    }

    const int m0 = row0 + wm * 64 + g;
    const int n0 = col0 + wn * 32 + 2 * q;
    #pragma unroll
    for (int i = 0; i < 4; i++) {
        #pragma unroll
        for (int j = 0; j < 4; j++) {
            int c = n0 + j * 8;
            float b0 = 0.f, b1 = 0.f;
            if (BIAS) { b0 = bias[c]; b1 = bias[c + 1]; }
            #pragma unroll
            for (int hh = 0; hh < 2; hh++) {
                int r = m0 + i * 16 + hh * 8;
                float v0 = acc[i][j][hh * 2 + 0] + b0;
                float v1 = acc[i][j][hh * 2 + 1] + b1;
                if (RES) {
                    const float* rp = res + (size_t)r * N + c;
                    v0 += rp[0]; v1 += rp[1];
                }
                if (RELU) { v0 = fmaxf(v0, 0.f); v1 = fmaxf(v1, 0.f); }
                if (PACKOUT) {
                    uint2* cp = (uint2*)((uint32_t*)C + (size_t)r * N + c);
                    *cp = packpair(v0, v1);
                } else {
                    float2* cp = (float2*)(C + (size_t)r * N + c);
                    *cp = make_float2(v0, v1);
                }
            }
        }
    }
}

// ======================= QK^T via packed bf16 mma ============================
__global__ void __launch_bounds__(256, 2)
qk_mma(const uint32_t* __restrict__ qkv, float* __restrict__ S) {
    if (blockIdx.x > blockIdx.y) return;
    extern __shared__ float smem_f[];
    uint32_t* As = (uint32_t*)smem_f;
    uint32_t* Bs = (uint32_t*)smem_f + 2*TILE_F;

    const int tid = threadIdx.x;
    const int wid = tid >> 5;
    const int lane = tid & 31;
    const int g = lane >> 2, q = lane & 3;
    const int wm = wid & 1, wn = wid >> 1;

    const int row0 = blockIdx.y * 128;
    const int col0 = blockIdx.x * 128;
    const int b = blockIdx.z >> 3, h = blockIdx.z & 7;
    const uint32_t* Ap = qkv + ((size_t)b*TT + row0) * QKVS + h*HD;
    const uint32_t* Bp = qkv + 512 + ((size_t)b*TT + col0) * QKVS + h*HD;

    const uint32_t sA0 = smem_u32(As);
    const uint32_t sB0 = smem_u32(Bs);

    int lrow[4], lc4[4];
    #pragma unroll
    for (int j = 0; j < 4; j++) {
        int i = tid + j * 256;
        lrow[j] = i >> 3;
        lc4[j] = i & 7;
    }

    auto load_stage = [&](int buf, int kt) {
        const int k0 = kt << 5;
        const uint32_t offA = sA0 + buf * TILE_F * 4;
        const uint32_t offB = sB0 + buf * TILE_F * 4;
        #pragma unroll
        for (int j = 0; j < 4; j++) {
            uint32_t so = (uint32_t)(lrow[j] * 36 + lc4[j] * 4) * 4;
            cp16(offA + so, Ap + (size_t)lrow[j] * QKVS + k0 + lc4[j] * 4);
            cp16(offB + so, Bp + (size_t)lrow[j] * QKVS + k0 + lc4[j] * 4);
        }
        asm volatile("cp.async.commit_group;");
    };

    float acc[4][4][4];
    #pragma unroll
    for (int i = 0; i < 4; i++)
        #pragma unroll
        for (int j = 0; j < 4; j++)
            #pragma unroll
            for (int t = 0; t < 4; t++) acc[i][j][t] = 0.0f;

    load_stage(0, 0);

    int buf = 0;
    for (int kt = 0; kt < 2; kt++) {
        asm volatile("cp.async.wait_group 0;");
        __syncthreads();
        if (kt == 0) load_stage(1, 1);

        const uint32_t* as = As + buf * TILE_F + (wm * 64 + g) * 36 + 2 * q;
        const uint32_t* bs = Bs + buf * TILE_F + (wn * 32 + g) * 36 + 2 * q;
        #pragma unroll
        for (int s = 0; s < 2; s++) {
            const int k0 = s * 16;
            uint32_t ah[4][4], al[4][4], bh[4][2], bl[4][2];
            #pragma unroll
            for (int i = 0; i < 4; i++) {
                const uint32_t* p = as + i * 16 * 36 + k0;
                unpk(*(const uint2*)(p),              ah[i][0], al[i][0]);
                unpk(*(const uint2*)(p + 8 * 36),     ah[i][1], al[i][1]);
                unpk(*(const uint2*)(p + 8),          ah[i][2], al[i][2]);
                unpk(*(const uint2*)(p + 8 * 36 + 8), ah[i][3], al[i][3]);
            }
            #pragma unroll
            for (int j = 0; j < 4; j++) {
                const uint32_t* p = bs + j * 8 * 36 + k0;
                unpk(*(const uint2*)(p),     bh[j][0], bl[j][0]);
                unpk(*(const uint2*)(p + 8), bh[j][1], bl[j][1]);
            }
            #pragma unroll
            for (int i = 0; i < 4; i++)
                #pragma unroll
                for (int j = 0; j < 4; j++) {
                    mma_bf16(acc[i][j], ah[i], bl[j]);
                    mma_bf16(acc[i][j], al[i], bh[j]);
                    mma_bf16(acc[i][j], ah[i], bh[j]);
                }
        }
        buf ^= 1;
    }

    float* Sp = S + (size_t)blockIdx.z * TT * TT;
    const int m0 = row0 + wm * 64 + g;
    const int n0 = col0 + wn * 32 + 2 * q;
    #pragma unroll
    for (int i = 0; i < 4; i++)
        #pragma unroll
        for (int j = 0; j < 4; j++) {
            int c = n0 + j * 8;
            #pragma unroll
            for (int hh = 0; hh < 2; hh++) {
                int r = m0 + i * 16 + hh * 8;
                float2* cp = (float2*)(Sp + (size_t)r * TT + c);
                *cp = make_float2(acc[i][j][hh*2+0] * 0.125f, acc[i][j][hh*2+1] * 0.125f);
            }
        }
}

// ======================= P @ V via bf16 mma ==================================
// A = P fp32 (split in-kernel), B = vT packed.
#define AV_AF (128*36)
#define AV_BF (64*36)
__global__ void __launch_bounds__(256, 2)
av_mma(const float* __restrict__ P, const uint32_t* __restrict__ vT,
       uint32_t* __restrict__ y) {
    extern __shared__ float smem_f[];
    float* As = smem_f;                              // fp32 P tile
    uint32_t* Bs = (uint32_t*)smem_f + 2*AV_AF;      // packed vT tile

    const int tid = threadIdx.x;
    const int wid = tid >> 5;
    const int lane = tid & 31;
    const int g = lane >> 2, q = lane & 3;
    const int wm = wid & 3, wn = wid >> 2;

    const int row0 = blockIdx.x * 128;
    const int b = blockIdx.z >> 3, h = blockIdx.z & 7;
    const float* Ap = P + (size_t)blockIdx.z * TT * TT + (size_t)row0 * TT;
    const uint32_t* Bp = vT + ((size_t)b*EE + h*HD) * TT;

    const uint32_t sA0 = smem_u32(As);
    const uint32_t sB0 = smem_u32(Bs);

    const int NK = (row0 >> 5) + 4;

    int arow[4], ac4[4], brow[2], bc4[2];
    #pragma unroll
    for (int j = 0; j < 4; j++) {
        int i = tid + j * 256;
        arow[j] = i >> 3; ac4[j] = i & 7;
    }
    #pragma unroll
    for (int j = 0; j < 2; j++) {
        int i = tid + j * 256;
        brow[j] = i >> 3; bc4[j] = i & 7;
    }

    auto load_stage = [&](int buf, int kt) {
        const int k0 = kt << 5;
        const uint32_t offA = sA0 + buf * AV_AF * 4;
        const uint32_t offB = sB0 + buf * AV_BF * 4;
        #pragma unroll
        for (int j = 0; j < 4; j++) {
            uint32_t so = (uint32_t)(arow[j] * 36 + ac4[j] * 4) * 4;
            cp16(offA + so, Ap + (size_t)arow[j] * TT + k0 + ac4[j] * 4);
        }
        #pragma unroll
        for (int j = 0; j < 2; j++) {
            uint32_t so = (uint32_t)(brow[j] * 36 + bc4[j] * 4) * 4;
            cp16(offB + so, Bp + (size_t)brow[j] * TT + k0 + bc4[j] * 4);
        }
        asm volatile("cp.async.commit_group;");
    };

    float acc[2][4][4];
    #pragma unroll
    for (int i = 0; i < 2; i++)
        #pragma unroll
        for (int j = 0; j < 4; j++)
            #pragma unroll
            for (int t = 0; t < 4; t++) acc[i][j][t] = 0.0f;

    load_stage(0, 0);

    int buf = 0;
    for (int kt = 0; kt < NK; kt++) {
        asm volatile("cp.async.wait_group 0;");
        __syncthreads();
        if (kt + 1 < NK) load_stage(buf ^ 1, kt + 1);

        const float* as = As + buf * AV_AF + (wm * 32 + g) * 36 + 2 * q;
        const uint32_t* bs = Bs + buf * AV_BF + (wn * 32 + g) * 36 + 2 * q;
        #pragma unroll
        for (int s = 0; s < 2; s++) {
            const int k0 = s * 16;
            uint32_t ah[2][4], al[2][4], bh[4][2], bl[4][2];
            #pragma unroll
            for (int i = 0; i < 2; i++) {
                const float* p = as + i * 16 * 36 + k0;
                float2 x0 = *(const float2*)(p);
                float2 x1 = *(const float2*)(p + 8 * 36);
                float2 x2 = *(const float2*)(p + 8);
                float2 x3 = *(const float2*)(p + 8 * 36 + 8);
                ah[i][0] = pack2_hi(x0.x, x0.y); al[i][0] = pack2_lo(x0.x, x0.y, ah[i][0]);
                ah[i][1] = pack2_hi(x1.x, x1.y); al[i][1] = pack2_lo(x1.x, x1.y, ah[i][1]);
                ah[i][2] = pack2_hi(x2.x, x2.y); al[i][2] = pack2_lo(x2.x, x2.y, ah[i][2]);
                ah[i][3] = pack2_hi(x3.x, x3.y); al[i][3] = pack2_lo(x3.x, x3.y, ah[i][3]);
            }
            #pragma unroll
            for (int j = 0; j < 4; j++) {
                const uint32_t* p = bs + j * 8 * 36 + k0;
                unpk(*(const uint2*)(p),     bh[j][0], bl[j][0]);
                unpk(*(const uint2*)(p + 8), bh[j][1], bl[j][1]);
            }
            #pragma unroll
            for (int i = 0; i < 2; i++)
                #pragma unroll
                for (int j = 0; j < 4; j++) {
                    mma_bf16(acc[i][j], ah[i], bl[j]);
                    mma_bf16(acc[i][j], al[i], bh[j]);
                    mma_bf16(acc[i][j], ah[i], bh[j]);
                }
        }
        buf ^= 1;
    }

    const int m0 = row0 + wm * 32 + g;
    const int n0 = wn * 32 + 2 * q;
    #pragma unroll
    for (int i = 0; i < 2; i++)
        #pragma unroll
        for (int j = 0; j < 4; j++) {
            int c = n0 + j * 8;
            #pragma unroll
            for (int hh = 0; hh < 2; hh++) {
                int r = m0 + i * 16 + hh * 8;
                uint2* cp = (uint2*)(y + ((size_t)b*TT + r) * EE + h*HD + c);
                *cp = packpair(acc[i][j][hh*2+0], acc[i][j][hh*2+1]);
            }
        }
}

// ---------------- transpose + pack: W[K,N] -> WT_packed[N,K] -----------------
__global__ void transpose_pack_kernel(const float* __restrict__ W, uint32_t* __restrict__ WT,
                                      int K, int N) {
    __shared__ float t[32][33];
    int n0 = blockIdx.x * 32, k0 = blockIdx.y * 32;
    int x = threadIdx.x, y = threadIdx.y;
    #pragma unroll
    for (int j = 0; j < 32; j += 8)
        t[y + j][x] = W[(size_t)(k0 + y + j) * N + n0 + x];
    __syncthreads();
    #pragma unroll
    for (int j = 0; j < 32; j += 8)
        WT[(size_t)(n0 + y + j) * K + k0 + x] = packelem(t[x][y + j]);
}

// padded transpose + pack (zero fill)
__global__ void pad_transpose_pack_kernel(const float* __restrict__ W, uint32_t* __restrict__ WT,
                                          int K, int N, int Kp, int Np) {
    __shared__ float t[32][33];
    int n0 = blockIdx.x * 32, k0 = blockIdx.y * 32;
    int x = threadIdx.x, y = threadIdx.y;
    #pragma unroll
    for (int j = 0; j < 32; j += 8) {
        int kk = k0 + y + j, nn = n0 + x;
        t[y + j][x] = (kk < K && nn < N) ? W[(size_t)kk * N + nn] : 0.0f;
    }
    __syncthreads();
    #pragma unroll
    for (int j = 0; j < 32; j += 8)
        WT[(size_t)(n0 + y + j) * Kp + k0 + x] = packelem(t[x][y + j]);
}

__global__ void pad_b1_kernel(const float* __restrict__ b1, float* __restrict__ b1p) {
    int l = blockIdx.x, tid = threadIdx.x;
    b1p[l * HIDP + tid] = (tid < HIDN) ? b1[l * HIDN + tid] : 0.0f;
}

// transpose packed V -> vT[b][e][s]
__global__ void vtrans_kernel(const uint32_t* __restrict__ qkv, uint32_t* __restrict__ vT) {
    __shared__ uint32_t t[32][33];
    int s0 = blockIdx.x * 32, e0 = blockIdx.y * 32, b = blockIdx.z;
    int x = threadIdx.x, y = threadIdx.y;
    #pragma unroll
    for (int j = 0; j < 32; j += 8)
        t[y + j][x] = qkv[((size_t)b*TT + s0 + y + j) * QKVS + 1024 + e0 + x];
    __syncthreads();
    #pragma unroll
    for (int j = 0; j < 32; j += 8)
        vT[((size_t)b*EE + e0 + y + j) * TT + s0 + x] = t[x][y + j];
}

// ---------------- embed ------------------------------------------------------
__global__ void embed_kernel(const int* __restrict__ idx,
                             const float* __restrict__ tok,
                             const float* __restrict__ pos,
                             float* __restrict__ x) {
    int row = blockIdx.x;
    int t = row & (TT - 1);
    int token = idx[row];
    const float4* tp = (const float4*)(tok + (size_t)token * EE);
    const float4* pp = (const float4*)(pos + (size_t)t * EE);
    float4* xp = (float4*)(x + (size_t)row * EE);
    int c = threadIdx.x;
    float4 a = tp[c], b = pp[c];
    xp[c] = make_float4(a.x + b.x, a.y + b.y, a.z + b.z, a.w + b.w);
}

// ---------------- layernorm -> PACKED output --------------------------------
__global__ void ln_kernel(const float* __restrict__ x, uint32_t* __restrict__ out,
                          const float* __restrict__ g, const float* __restrict__ b) {
    int row = blockIdx.x;
    int tid = threadIdx.x;
    const float4* xp = (const float4*)(x + (size_t)row * EE);
    float4 v = xp[tid];
    float s = v.x + v.y + v.z + v.w;
    __shared__ float red[4];
    for (int o = 16; o; o >>= 1) s += __shfl_xor_sync(~0u, s, o);
    if ((tid & 31) == 0) red[tid >> 5] = s;
    __syncthreads();
    float mean = (red[0] + red[1] + red[2] + red[3]) / (float)EE;
    float dx = v.x - mean, dy = v.y - mean, dz = v.z - mean, dw = v.w - mean;
    float ss = dx*dx + dy*dy + dz*dz + dw*dw;
    __syncthreads();
    for (int o = 16; o; o >>= 1) ss += __shfl_xor_sync(~0u, ss, o);
    if ((tid & 31) == 0) red[tid >> 5] = ss;
    __syncthreads();
    float var = (red[0] + red[1] + red[2] + red[3]) / (float)EE;
    float inv = 1.0f / sqrtf(var + 1e-5f);
    const float4* gp = (const float4*)g;
    const float4* bp = (const float4*)b;
    float4 gg = gp[tid], bb = bp[tid];
    float o0 = dx*inv*gg.x + bb.x, o1 = dy*inv*gg.y + bb.y;
    float o2 = dz*inv*gg.z + bb.z, o3 = dw*inv*gg.w + bb.w;
    uint2 p01 = packpair(o0, o1);
    uint2 p23 = packpair(o2, o3);
    uint4* op = (uint4*)(out + (size_t)row * EE);
    op[tid] = make_uint4(p01.x, p01.y, p23.x, p23.y);
}

// ---------------- causal softmax row -> writes attn map into d_out ----------
__global__ void softmax_kernel(const float* __restrict__ S, float* __restrict__ out) {
    int row = blockIdx.x;
    int t = row & (TT - 1);
    const float* sp = S + (size_t)row * TT;
    float* op = out + (size_t)row * TT;
    int tid = threadIdx.x;
    float vals[4];
    float m = -1e30f;
    #pragma unroll
    for (int i = 0; i < 4; i++) {
        int s = tid + i * 256;
        vals[i] = (s <= t) ? sp[s] : -1e30f;
        m = fmaxf(m, vals[i]);
    }
    __shared__ float red[8];
    for (int o = 16; o; o >>= 1) m = fmaxf(m, __shfl_xor_sync(~0u, m, o));
    if ((tid & 31) == 0) red[tid >> 5] = m;
    __syncthreads();
    m = red[0];
    #pragma unroll
    for (int i = 1; i < 8; i++) m = fmaxf(m, red[i]);
    float e[4];
    float ssum = 0.0f;
    #pragma unroll
    for (int i = 0; i < 4; i++) {
        int s = tid + i * 256;
        e[i] = (s <= t) ? expf(vals[i] - m) : 0.0f;
        ssum += e[i];
    }
    __syncthreads();
    for (int o = 16; o; o >>= 1) ssum += __shfl_xor_sync(~0u, ssum, o);
    if ((tid & 31) == 0) red[tid >> 5] = ssum;
    __syncthreads();
    float tot = 0.0f;
    #pragma unroll
    for (int i = 0; i < 8; i++) tot += red[i];
    float inv = 1.0f / tot;
    #pragma unroll
    for (int i = 0; i < 4; i++) {
        int s = tid + i * 256;
        op[s] = e[i] * inv;
    }
}

// ---------------- host orchestration ----------------------------------------
extern "C" void kernel_launch(void* const* d_in, const int* in_sizes, int n_in,
                              void* d_out, int out_size) {
    (void)in_sizes; (void)n_in; (void)out_size;
    const int*   idx     = (const int*)  d_in[0];
    const float* tok_emb = (const float*)d_in[1];
    const float* pos_emb = (const float*)d_in[2];
    const float* ln1_g   = (const float*)d_in[3];
    const float* ln1_b   = (const float*)d_in[4];
    const float* Wq      = (const float*)d_in[5];
    const float* Wk      = (const float*)d_in[6];
    const float* Wv      = (const float*)d_in[7];
    const float* Wo      = (const float*)d_in[8];
    const float* bo      = (const float*)d_in[9];
    const float* ln2_g   = (const float*)d_in[10];
    const float* ln2_b   = (const float*)d_in[11];
    const float* W1      = (const float*)d_in[12];
    const float* b1      = (const float*)d_in[13];
    const float* W2      = (const float*)d_in[14];
    const float* b2      = (const float*)d_in[15];
    const float* lnf_g   = (const float*)d_in[16];
    const float* lnf_b   = (const float*)d_in[17];
    const float* Wlm     = (const float*)d_in[18];

    float* out    = (float*)d_out;
    float* logits = out;
    float* attn   = out + LOGITS_N;

    float *gx, *gS, *gb1p;
    uint32_t *gh, *gqkv, *gy, *gu, *gvT, *gWlmT, *gWT, *gW1Tp, *gW2Tp;
    cudaGetSymbolAddress((void**)&gx, d_x);
    cudaGetSymbolAddress((void**)&gh, d_h);
    cudaGetSymbolAddress((void**)&gqkv, d_qkv);
    cudaGetSymbolAddress((void**)&gy, d_y);
    cudaGetSymbolAddress((void**)&gu, d_u);
    cudaGetSymbolAddress((void**)&gS, d_S);
    cudaGetSymbolAddress((void**)&gvT, d_vT);
    cudaGetSymbolAddress((void**)&gWlmT, d_WlmT);
    cudaGetSymbolAddress((void**)&gWT, d_WT);
    cudaGetSymbolAddress((void**)&gW1Tp, d_W1Tp);
    cudaGetSymbolAddress((void**)&gW2Tp, d_W2Tp);
    cudaGetSymbolAddress((void**)&gb1p, d_b1p);

    cudaFuncSetAttribute(mma_gemm<false,false,false,false,true>,
                         cudaFuncAttributeMaxDynamicSharedMemorySize, GEMM_SMEM);
    cudaFuncSetAttribute(mma_gemm<true,true,false,false,false>,
                         cudaFuncAttributeMaxDynamicSharedMemorySize, GEMM_SMEM);
    cudaFuncSetAttribute(mma_gemm<true,false,true,false,true>,
                         cudaFuncAttributeMaxDynamicSharedMemorySize, GEMM_SMEM);
    cudaFuncSetAttribute(mma_gemm<false,false,false,true,false>,
                         cudaFuncAttributeMaxDynamicSharedMemorySize, GEMM_SMEM);
    cudaFuncSetAttribute(qk_mma, cudaFuncAttributeMaxDynamicSharedMemorySize, GEMM_SMEM);
    cudaFuncSetAttribute(av_mma, cudaFuncAttributeMaxDynamicSharedMemorySize, AV_SMEM);

    // Weight prep: transpose + pack
    {
        dim3 tb(32, 8);
        for (int l = 0; l < LL; l++) {
            uint32_t* base = gWT + (size_t)l * 4 * EE * EE;
            transpose_pack_kernel<<<dim3(EE/32, EE/32), tb>>>(Wq + (size_t)l*EE*EE, base,                 EE, EE);
            transpose_pack_kernel<<<dim3(EE/32, EE/32), tb>>>(Wk + (size_t)l*EE*EE, base + (size_t)512*EE, EE, EE);
            transpose_pack_kernel<<<dim3(EE/32, EE/32), tb>>>(Wv + (size_t)l*EE*EE, base + (size_t)1024*EE, EE, EE);
            transpose_pack_kernel<<<dim3(EE/32, EE/32), tb>>>(Wo + (size_t)l*EE*EE, base + (size_t)1536*EE, EE, EE);
            pad_transpose_pack_kernel<<<dim3(HIDP/32, EE/32), tb>>>(
                W1 + (size_t)l*EE*HIDN, gW1Tp + (size_t)l*HIDP*EE, EE, HIDN, EE, HIDP);
            pad_transpose_pack_kernel<<<dim3(EE/32, HIDP/32), tb>>>(
                W2 + (size_t)l*HIDN*EE, gW2Tp + (size_t)l*EE*HIDP, HIDN, EE, HIDP, EE);
        }
        pad_b1_kernel<<<LL, HIDP>>>(b1, gb1p);
        transpose_pack_kernel<<<dim3(VV/32, EE/32), tb>>>(Wlm, gWlmT, EE, VV);
    }

    embed_kernel<<<BT, 128>>>(idx, tok_emb, pos_emb, gx);

    for (int l = 0; l < LL; l++) {
        uint32_t* base = gWT + (size_t)l * 4 * EE * EE;
        const uint32_t* qkvT = base;
        const uint32_t* woT  = base + (size_t)1536*EE;
        float* attn_l = attn + (size_t)l * ATT_PER_L;

        ln_kernel<<<BT, 128>>>(gx, gh, ln1_g + l*EE, ln1_b + l*EE);

        // fused QKV (packed in, packed out)
        mma_gemm<false,false,false,false,true><<<dim3(QKVS/128, BT/128), 256, GEMM_SMEM>>>(
            gh, qkvT, nullptr, nullptr, (float*)gqkv, BT, QKVS, EE);

        qk_mma<<<dim3(8, 8, BB*HH), 256, GEMM_SMEM>>>(gqkv, gS);
        softmax_kernel<<<BHT, 256>>>(gS, attn_l);
        vtrans_kernel<<<dim3(TT/32, EE/32, BB), dim3(32, 8)>>>(gqkv, gvT);
        av_mma<<<dim3(8, 1, BB*HH), 256, AV_SMEM>>>(attn_l, gvT, gy);

        // x = x + y @ Wo + bo  (packed A, fp32 out + residual)
        mma_gemm<true,true,false,false,false><<<dim3(EE/128, BT/128), 256, GEMM_SMEM>>>(
            gy, woT, bo + l*EE, gx, gx, BT, EE, EE);

        ln_kernel<<<BT, 128>>>(gx, gh, ln2_g + l*EE, ln2_b + l*EE);

        // u = relu(h @ W1 + b1)  packed out
        mma_gemm<true,false,true,false,true><<<dim3(HIDP/128, BT/128), 256, GEMM_SMEM>>>(
            gh, gW1Tp + (size_t)l*HIDP*EE, gb1p + l*HIDP, nullptr, (float*)gu, BT, HIDP, EE);
        // x = x + u @ W2 + b2
        mma_gemm<true,true,false,false,false><<<dim3(EE/128, BT/128), 256, GEMM_SMEM>>>(
            gu, gW2Tp + (size_t)l*EE*HIDP, b2 + l*EE, gx, gx, BT, EE, HIDP);
    }

    ln_kernel<<<BT, 128>>>(gx, gh, lnf_g, lnf_b);
    // logits: packed A/B, fp32 out, M-fastest grid
    mma_gemm<false,false,false,true,false><<<dim3(BT/128, VV/128), 256, GEMM_SMEM>>>(
        gh, gWlmT, nullptr, nullptr, logits, BT, VV, EE);
}

// round 14
// speedup vs baseline: 1.2177x; 1.1839x over previous
#include <cuda_runtime.h>
#include <cuda_bf16.h>
#include <cuda_fp16.h>
#include <cstdint>
#include <cstddef>

// Problem dims
#define BB 4
#define TT 1024
#define EE 512
#define HH 8
#define LL 4
#define VV 32000
#define HIDN 100
#define HIDP 128
#define HD 64
#define BT (BB*TT)          // 4096
#define BHT (BB*HH*TT)      // 32768
#define QKVS 1536           // packed qkv row stride
#define ATT_PER_L ((size_t)BB*HH*TT*TT)
#define LOGITS_N ((size_t)BT*VV)

// ---------------- scratch (device globals; no allocations allowed) ----------
// Packed format: uint32 = 16_hi(f) | 16_lo(f - hi) << 16   (bf16 or fp16)
__device__ float    d_x[BT*EE];                   // residual stream (fp32)
__device__ uint32_t d_h[BT*EE];                   // packed LN output
__device__ uint32_t d_qkv[(size_t)BT*QKVS];       // packed q,k,v
__device__ uint32_t d_y[BT*EE];                   // packed attn output
__device__ uint32_t d_u[BT*HIDP];                 // packed ffn hidden
__device__ float    d_S[(size_t)BB*HH*TT*TT];     // raw scores fp32, 128 MB
__device__ uint32_t d_vT[(size_t)BB*EE*TT];       // packed V^T [b][e][s]
__device__ __half   d_Wlm16[(size_t)VV*EE];       // Wlm^T as fp16 [V,E]
__device__ uint32_t d_WT[(size_t)LL*4*EE*EE];     // packed per-layer qkvT+woT
__device__ uint32_t d_W1Tp[(size_t)LL*HIDP*EE];   // packed padded W1^T
__device__ uint32_t d_W2Tp[(size_t)LL*EE*HIDP];   // packed padded W2^T
__device__ float    d_b1p[LL*HIDP];

// ======================= helpers =============================================
#define TILE_F (128*36)           // elems per smem tile (padded rows)
#define GEMM_SMEM (4*TILE_F*4)
#define AV_SMEM  (2*(128*36 + 64*36)*4)
// logits kernel smem: A 2x(128*36 words), B 2x(128*40 halfs)
#define LMPAD 40
#define LM_AS (128*36)
#define LM_BS (128*LMPAD)
#define LM_SMEM (2*LM_AS*4 + 2*LM_BS*2)

__device__ __forceinline__ uint32_t smem_u32(const void* p) {
    uint32_t a;
    asm("{ .reg .u64 t; cvta.to.shared.u64 t, %1; cvt.u32.u64 %0, t; }"
        : "=r"(a) : "l"(p));
    return a;
}
__device__ __forceinline__ void cp16(uint32_t saddr, const void* g) {
    asm volatile("cp.async.cg.shared.global [%0], [%1], 16;" :: "r"(saddr), "l"(g));
}
__device__ __forceinline__ uint32_t pack2_hi(float f0, float f1) {
    uint32_t r;
    asm("cvt.rn.bf16x2.f32 %0, %1, %2;" : "=r"(r) : "f"(f1), "f"(f0));
    return r;
}
__device__ __forceinline__ uint32_t pack2_lo(float f0, float f1, uint32_t hi) {
    float h0 = __uint_as_float(hi << 16);
    float h1 = __uint_as_float(hi & 0xffff0000u);
    uint32_t r;
    asm("cvt.rn.bf16x2.f32 %0, %1, %2;" : "=r"(r) : "f"(f1 - h1), "f"(f0 - h0));
    return r;
}
__device__ __forceinline__ uint32_t packelem(float f) {
    uint32_t H = pack2_hi(f, 0.0f);
    float hf = __uint_as_float(H << 16);
    uint32_t L = pack2_hi(f - hf, 0.0f);
    return (H & 0xffffu) | (L << 16);
}
__device__ __forceinline__ uint2 packpair(float f0, float f1) {
    uint32_t H = pack2_hi(f0, f1);
    uint32_t L = pack2_lo(f0, f1, H);
    return make_uint2(__byte_perm(H, L, 0x5410), __byte_perm(H, L, 0x7632));
}
// fp16 pair pack: per element word = f16_hi | f16_lo<<16
__device__ __forceinline__ uint2 packpair16(float f0, float f1) {
    uint32_t H;
    asm("cvt.rn.f16x2.f32 %0, %1, %2;" : "=r"(H) : "f"(f1), "f"(f0));
    float h0, h1;
    asm("{.reg .b16 a,b;\n\t mov.b32 {a,b}, %2;\n\t cvt.f32.f16 %0, a;\n\t cvt.f32.f16 %1, b;}"
        : "=f"(h0), "=f"(h1) : "r"(H));
    uint32_t L;
    asm("cvt.rn.f16x2.f32 %0, %1, %2;" : "=r"(L) : "f"(f1 - h1), "f"(f0 - h0));
    return make_uint2(__byte_perm(H, L, 0x5410), __byte_perm(H, L, 0x7632));
}
__device__ __forceinline__ void unpk(uint2 w, uint32_t& hi, uint32_t& lo) {
    hi = __byte_perm(w.x, w.y, 0x5410);
    lo = __byte_perm(w.x, w.y, 0x7632);
}
__device__ __forceinline__ void mma_bf16(float c[4], const uint32_t a[4], const uint32_t b[2]) {
    asm volatile(
        "mma.sync.aligned.m16n8k16.row.col.f32.bf16.bf16.f32 "
        "{%0,%1,%2,%3}, {%4,%5,%6,%7}, {%8,%9}, {%0,%1,%2,%3};"
        : "+f"(c[0]), "+f"(c[1]), "+f"(c[2]), "+f"(c[3])
        : "r"(a[0]), "r"(a[1]), "r"(a[2]), "r"(a[3]), "r"(b[0]), "r"(b[1]));
}
__device__ __forceinline__ void mma_f16(float c[4], const uint32_t a[4], const uint32_t b[2]) {
    asm volatile(
        "mma.sync.aligned.m16n8k16.row.col.f32.f16.f16.f32 "
        "{%0,%1,%2,%3}, {%4,%5,%6,%7}, {%8,%9}, {%0,%1,%2,%3};"
        : "+f"(c[0]), "+f"(c[1]), "+f"(c[2]), "+f"(c[3])
        : "r"(a[0]), "r"(a[1]), "r"(a[2]), "r"(a[3]), "r"(b[0]), "r"(b[1]));
}

// ======================= packed bf16 mma GEMM (3-term) =======================
template <bool BIAS, bool RES, bool RELU, bool PACKOUT>
__global__ void __launch_bounds__(256, 2)
mma_gemm(const uint32_t* __restrict__ A, const uint32_t* __restrict__ BT_,
         const float* __restrict__ bias, const float* __restrict__ res,
         float* __restrict__ C, int M, int N, int K) {
    extern __shared__ float smem_f[];
    uint32_t* As = (uint32_t*)smem_f;
    uint32_t* Bs = (uint32_t*)smem_f + 2*TILE_F;

    const int tid = threadIdx.x;
    const int wid = tid >> 5;
    const int lane = tid & 31;
    const int g = lane >> 2, q = lane & 3;
    const int wm = wid & 1, wn = wid >> 1;

    const int row0 = blockIdx.y * 128;
    const int col0 = blockIdx.x * 128;
    const uint32_t* Ap = A + (size_t)row0 * K;
    const uint32_t* Bp = BT_ + (size_t)col0 * K;

    const uint32_t sA0 = smem_u32(As);
    const uint32_t sB0 = smem_u32(Bs);

    const int NK = K >> 5;

    int lrow[4], lc4[4];
    #pragma unroll
    for (int j = 0; j < 4; j++) {
        int i = tid + j * 256;
        lrow[j] = i >> 3;
        lc4[j] = i & 7;
    }

    auto load_stage = [&](int buf, int kt) {
        const int k0 = kt << 5;
        const uint32_t offA = sA0 + buf * TILE_F * 4;
        const uint32_t offB = sB0 + buf * TILE_F * 4;
        #pragma unroll
        for (int j = 0; j < 4; j++) {
            uint32_t so = (uint32_t)(lrow[j] * 36 + lc4[j] * 4) * 4;
            cp16(offA + so, Ap + (size_t)lrow[j] * K + k0 + lc4[j] * 4);
            cp16(offB + so, Bp + (size_t)lrow[j] * K + k0 + lc4[j] * 4);
        }
        asm volatile("cp.async.commit_group;");
    };

    float acc[4][4][4];
    #pragma unroll
    for (int i = 0; i < 4; i++)
        #pragma unroll
        for (int j = 0; j < 4; j++)
            #pragma unroll
            for (int t = 0; t < 4; t++) acc[i][j][t] = 0.0f;

    load_stage(0, 0);

    int buf = 0;
    for (int kt = 0; kt < NK; kt++) {
        asm volatile("cp.async.wait_group 0;");
        __syncthreads();
        if (kt + 1 < NK) load_stage(buf ^ 1, kt + 1);

        const uint32_t* as = As + buf * TILE_F + (wm * 64 + g) * 36 + 2 * q;
        const uint32_t* bs = Bs + buf * TILE_F + (wn * 32 + g) * 36 + 2 * q;
        #pragma unroll
        for (int s = 0; s < 2; s++) {
            const int k0 = s * 16;
            uint32_t ah[4][4], al[4][4], bh[4][2], bl[4][2];
            #pragma unroll
            for (int i = 0; i < 4; i++) {
                const uint32_t* p = as + i * 16 * 36 + k0;
                unpk(*(const uint2*)(p),              ah[i][0], al[i][0]);
                unpk(*(const uint2*)(p + 8 * 36),     ah[i][1], al[i][1]);
                unpk(*(const uint2*)(p + 8),          ah[i][2], al[i][2]);
                unpk(*(const uint2*)(p + 8 * 36 + 8), ah[i][3], al[i][3]);
            }
            #pragma unroll
            for (int j = 0; j < 4; j++) {
                const uint32_t* p = bs + j * 8 * 36 + k0;
                unpk(*(const uint2*)(p),     bh[j][0], bl[j][0]);
                unpk(*(const uint2*)(p + 8), bh[j][1], bl[j][1]);
            }
            #pragma unroll
            for (int i = 0; i < 4; i++)
                #pragma unroll
                for (int j = 0; j < 4; j++) {
                    mma_bf16(acc[i][j], ah[i], bl[j]);
                    mma_bf16(acc[i][j], al[i], bh[j]);
                    mma_bf16(acc[i][j], ah[i], bh[j]);
                }
        }
        buf ^= 1;
    }

    const int m0 = row0 + wm * 64 + g;
    const int n0 = col0 + wn * 32 + 2 * q;
    #pragma unroll
    for (int i = 0; i < 4; i++) {
        #pragma unroll
        for (int j = 0; j < 4; j++) {
            int c = n0 + j * 8;
            float b0 = 0.f, b1 = 0.f;
            if (BIAS) { b0 = bias[c]; b1 = bias[c + 1]; }
            #pragma unroll
            for (int hh = 0; hh < 2; hh++) {
                int r = m0 + i * 16 + hh * 8;
                float v0 = acc[i][j][hh * 2 + 0] + b0;
                float v1 = acc[i][j][hh * 2 + 1] + b1;
                if (RES) {
                    const float* rp = res + (size_t)r * N + c;
                    v0 += rp[0]; v1 += rp[1];
                }
                if (RELU) { v0 = fmaxf(v0, 0.f); v1 = fmaxf(v1, 0.f); }
                if (PACKOUT) {
                    uint2* cp = (uint2*)((uint32_t*)C + (size_t)r * N + c);
                    *cp = packpair(v0, v1);
                } else {
                    float2* cp = (float2*)(C + (size_t)r * N + c);
                    *cp = make_float2(v0, v1);
                }
            }
        }
    }
}

// ======================= logits GEMM: fp16 2-term ============================
// C[M,N] = A[M,K] @ Wlm; A packed fp16-pair uint32, B = Wlm^T plain fp16 [N,K].
// M-fastest grid (blockIdx.x = M block) for L2-friendly weight streaming.
__global__ void __launch_bounds__(256, 2)
lm_gemm(const uint32_t* __restrict__ A, const __half* __restrict__ BT_,
        float* __restrict__ C, int M, int N, int K) {
    extern __shared__ float smem_f[];
    uint32_t* As = (uint32_t*)smem_f;                       // 2*LM_AS words
    uint32_t* Bs = (uint32_t*)smem_f + 2*LM_AS;             // 2*LM_BS halfs

    const int tid = threadIdx.x;
    const int wid = tid >> 5;
    const int lane = tid & 31;
    const int g = lane >> 2, q = lane & 3;
    const int wm = wid & 1, wn = wid >> 1;

    const int row0 = blockIdx.x * 128;      // M-fastest
    const int col0 = blockIdx.y * 128;
    const uint32_t* Ap = A + (size_t)row0 * K;
    const __half* Bp = BT_ + (size_t)col0 * K;

    const uint32_t sA0 = smem_u32(As);
    const uint32_t sB0 = smem_u32(Bs);

    const int NK = K >> 5;                  // 16

    int lrow[4], lc4[4];
    #pragma unroll
    for (int j = 0; j < 4; j++) {
        int i = tid + j * 256;
        lrow[j] = i >> 3;
        lc4[j] = i & 7;
    }
    int brow[2], bc4[2];
    #pragma unroll
    for (int j = 0; j < 2; j++) {
        int i = tid + j * 256;
        brow[j] = i >> 2;
        bc4[j] = i & 3;
    }

    auto load_stage = [&](int buf, int kt) {
        const int k0 = kt << 5;
        const uint32_t offA = sA0 + buf * LM_AS * 4;
        const uint32_t offB = sB0 + buf * LM_BS * 2;
        #pragma unroll
        for (int j = 0; j < 4; j++) {
            uint32_t so = (uint32_t)(lrow[j] * 36 + lc4[j] * 4) * 4;
            cp16(offA + so, Ap + (size_t)lrow[j] * K + k0 + lc4[j] * 4);
        }
        #pragma unroll
        for (int j = 0; j < 2; j++) {
            uint32_t so = (uint32_t)(brow[j] * 80 + bc4[j] * 16);
            cp16(offB + so, Bp + (size_t)brow[j] * K + k0 + bc4[j] * 8);
        }
        asm volatile("cp.async.commit_group;");
    };

    float acc[4][4][4];
    #pragma unroll
    for (int i = 0; i < 4; i++)
        #pragma unroll
        for (int j = 0; j < 4; j++)
            #pragma unroll
            for (int t = 0; t < 4; t++) acc[i][j][t] = 0.0f;

    load_stage(0, 0);

    int buf = 0;
    for (int kt = 0; kt < NK; kt++) {
        asm volatile("cp.async.wait_group 0;");
        __syncthreads();
        if (kt + 1 < NK) load_stage(buf ^ 1, kt + 1);

        const uint32_t* as = As + buf * LM_AS + (wm * 64 + g) * 36 + 2 * q;
        const uint32_t* bsw = Bs + buf * (LM_BS / 2) + (wn * 32 + g) * (LMPAD / 2);
        #pragma unroll
        for (int s = 0; s < 2; s++) {
            const int k0 = s * 16;
            uint32_t ah[4][4], al[4][4], bh[4][2];
            #pragma unroll
            for (int i = 0; i < 4; i++) {
                const uint32_t* p = as + i * 16 * 36 + k0;
                unpk(*(const uint2*)(p),              ah[i][0], al[i][0]);
                unpk(*(const uint2*)(p + 8 * 36),     ah[i][1], al[i][1]);
                unpk(*(const uint2*)(p + 8),          ah[i][2], al[i][2]);
                unpk(*(const uint2*)(p + 8 * 36 + 8), ah[i][3], al[i][3]);
            }
            #pragma unroll
            for (int j = 0; j < 4; j++) {
                const uint32_t* p = bsw + j * 8 * (LMPAD / 2) + s * 8 + q;
                bh[j][0] = p[0];
                bh[j][1] = p[4];
            }
            #pragma unroll
            for (int i = 0; i < 4; i++)
                #pragma unroll
                for (int j = 0; j < 4; j++) {
                    mma_f16(acc[i][j], al[i], bh[j]);
                    mma_f16(acc[i][j], ah[i], bh[j]);
                }
        }
        buf ^= 1;
    }

    const int m0 = row0 + wm * 64 + g;
    const int n0 = col0 + wn * 32 + 2 * q;
    #pragma unroll
    for (int i = 0; i < 4; i++)
        #pragma unroll
        for (int j = 0; j < 4; j++) {
            int c = n0 + j * 8;
            #pragma unroll
            for (int hh = 0; hh < 2; hh++) {
                int r = m0 + i * 16 + hh * 8;
                float2* cp = (float2*)(C + (size_t)r * N + c);
                *cp = make_float2(acc[i][j][hh * 2 + 0], acc[i][j][hh * 2 + 1]);
            }
        }
}

// ======================= QK^T via packed bf16 mma ============================
__global__ void __launch_bounds__(256, 2)
qk_mma(const uint32_t* __restrict__ qkv, float* __restrict__ S) {
    if (blockIdx.x > blockIdx.y) return;
    extern __shared__ float smem_f[];
    uint32_t* As = (uint32_t*)smem_f;
    uint32_t* Bs = (uint32_t*)smem_f + 2*TILE_F;

    const int tid = threadIdx.x;
    const int wid = tid >> 5;
    const int lane = tid & 31;
    const int g = lane >> 2, q = lane & 3;
    const int wm = wid & 1, wn = wid >> 1;

    const int row0 = blockIdx.y * 128;
    const int col0 = blockIdx.x * 128;
    const int b = blockIdx.z >> 3, h = blockIdx.z & 7;
    const uint32_t* Ap = qkv + ((size_t)b*TT + row0) * QKVS + h*HD;
    const uint32_t* Bp = qkv + 512 + ((size_t)b*TT + col0) * QKVS + h*HD;

    const uint32_t sA0 = smem_u32(As);
    const uint32_t sB0 = smem_u32(Bs);

    int lrow[4], lc4[4];
    #pragma unroll
    for (int j = 0; j < 4; j++) {
        int i = tid + j * 256;
        lrow[j] = i >> 3;
        lc4[j] = i & 7;
    }

    auto load_stage = [&](int buf, int kt) {
        const int k0 = kt << 5;
        const uint32_t offA = sA0 + buf * TILE_F * 4;
        const uint32_t offB = sB0 + buf * TILE_F * 4;
        #pragma unroll
        for (int j = 0; j < 4; j++) {
            uint32_t so = (uint32_t)(lrow[j] * 36 + lc4[j] * 4) * 4;
            cp16(offA + so, Ap + (size_t)lrow[j] * QKVS + k0 + lc4[j] * 4);
            cp16(offB + so, Bp + (size_t)lrow[j] * QKVS + k0 + lc4[j] * 4);
        }
        asm volatile("cp.async.commit_group;");
    };

    float acc[4][4][4];
    #pragma unroll
    for (int i = 0; i < 4; i++)
        #pragma unroll
        for (int j = 0; j < 4; j++)
            #pragma unroll
            for (int t = 0; t < 4; t++) acc[i][j][t] = 0.0f;

    load_stage(0, 0);

    int buf = 0;
    for (int kt = 0; kt < 2; kt++) {
        asm volatile("cp.async.wait_group 0;");
        __syncthreads();
        if (kt == 0) load_stage(1, 1);

        const uint32_t* as = As + buf * TILE_F + (wm * 64 + g) * 36 + 2 * q;
        const uint32_t* bs = Bs + buf * TILE_F + (wn * 32 + g) * 36 + 2 * q;
        #pragma unroll
        for (int s = 0; s < 2; s++) {
            const int k0 = s * 16;
            uint32_t ah[4][4], al[4][4], bh[4][2], bl[4][2];
            #pragma unroll
            for (int i = 0; i < 4; i++) {
                const uint32_t* p = as + i * 16 * 36 + k0;
                unpk(*(const uint2*)(p),              ah[i][0], al[i][0]);
                unpk(*(const uint2*)(p + 8 * 36),     ah[i][1], al[i][1]);
                unpk(*(const uint2*)(p + 8),          ah[i][2], al[i][2]);
                unpk(*(const uint2*)(p + 8 * 36 + 8), ah[i][3], al[i][3]);
            }
            #pragma unroll
            for (int j = 0; j < 4; j++) {
                const uint32_t* p = bs + j * 8 * 36 + k0;
                unpk(*(const uint2*)(p),     bh[j][0], bl[j][0]);
                unpk(*(const uint2*)(p + 8), bh[j][1], bl[j][1]);
            }
            #pragma unroll
            for (int i = 0; i < 4; i++)
                #pragma unroll
                for (int j = 0; j < 4; j++) {
                    mma_bf16(acc[i][j], ah[i], bl[j]);
                    mma_bf16(acc[i][j], al[i], bh[j]);
                    mma_bf16(acc[i][j], ah[i], bh[j]);
                }
        }
        buf ^= 1;
    }

    float* Sp = S + (size_t)blockIdx.z * TT * TT;
    const int m0 = row0 + wm * 64 + g;
    const int n0 = col0 + wn * 32 + 2 * q;
    #pragma unroll
    for (int i = 0; i < 4; i++)
        #pragma unroll
        for (int j = 0; j < 4; j++) {
            int c = n0 + j * 8;
            #pragma unroll
            for (int hh = 0; hh < 2; hh++) {
                int r = m0 + i * 16 + hh * 8;
                float2* cp = (float2*)(Sp + (size_t)r * TT + c);
                *cp = make_float2(acc[i][j][hh*2+0] * 0.125f, acc[i][j][hh*2+1] * 0.125f);
            }
        }
}

// ======================= P @ V via bf16 mma ==================================
#define AV_AF (128*36)
#define AV_BF (64*36)
__global__ void __launch_bounds__(256, 2)
av_mma(const float* __restrict__ P, const uint32_t* __restrict__ vT,
       uint32_t* __restrict__ y) {
    extern __shared__ float smem_f[];
    float* As = smem_f;
    uint32_t* Bs = (uint32_t*)smem_f + 2*AV_AF;

    const int tid = threadIdx.x;
    const int wid = tid >> 5;
    const int lane = tid & 31;
    const int g = lane >> 2, q = lane & 3;
    const int wm = wid & 3, wn = wid >> 2;

    const int row0 = blockIdx.x * 128;
    const int b = blockIdx.z >> 3, h = blockIdx.z & 7;
    const float* Ap = P + (size_t)blockIdx.z * TT * TT + (size_t)row0 * TT;
    const uint32_t* Bp = vT + ((size_t)b*EE + h*HD) * TT;

    const uint32_t sA0 = smem_u32(As);
    const uint32_t sB0 = smem_u32(Bs);

    const int NK = (row0 >> 5) + 4;

    int arow[4], ac4[4], brow[2], bc4[2];
    #pragma unroll
    for (int j = 0; j < 4; j++) {
        int i = tid + j * 256;
        arow[j] = i >> 3; ac4[j] = i & 7;
    }
    #pragma unroll
    for (int j = 0; j < 2; j++) {
        int i = tid + j * 256;
        brow[j] = i >> 3; bc4[j] = i & 7;
    }

    auto load_stage = [&](int buf, int kt) {
        const int k0 = kt << 5;
        const uint32_t offA = sA0 + buf * AV_AF * 4;
        const uint32_t offB = sB0 + buf * AV_BF * 4;
        #pragma unroll
        for (int j = 0; j < 4; j++) {
            uint32_t so = (uint32_t)(arow[j] * 36 + ac4[j] * 4) * 4;
            cp16(offA + so, Ap + (size_t)arow[j] * TT + k0 + ac4[j] * 4);
        }
        #pragma unroll
        for (int j = 0; j < 2; j++) {
            uint32_t so = (uint32_t)(brow[j] * 36 + bc4[j] * 4) * 4;
            cp16(offB + so, Bp + (size_t)brow[j] * TT + k0 + bc4[j] * 4);
        }
        asm volatile("cp.async.commit_group;");
    };

    float acc[2][4][4];
    #pragma unroll
    for (int i = 0; i < 2; i++)
        #pragma unroll
        for (int j = 0; j < 4; j++)
            #pragma unroll
            for (int t = 0; t < 4; t++) acc[i][j][t] = 0.0f;

    load_stage(0, 0);

    int buf = 0;
    for (int kt = 0; kt < NK; kt++) {
        asm volatile("cp.async.wait_group 0;");
        __syncthreads();
        if (kt + 1 < NK) load_stage(buf ^ 1, kt + 1);

        const float* as = As + buf * AV_AF + (wm * 32 + g) * 36 + 2 * q;
        const uint32_t* bs = Bs + buf * AV_BF + (wn * 32 + g) * 36 + 2 * q;
        #pragma unroll
        for (int s = 0; s < 2; s++) {
            const int k0 = s * 16;
            uint32_t ah[2][4], al[2][4], bh[4][2], bl[4][2];
            #pragma unroll
            for (int i = 0; i < 2; i++) {
                const float* p = as + i * 16 * 36 + k0;
                float2 x0 = *(const float2*)(p);
                float2 x1 = *(const float2*)(p + 8 * 36);
                float2 x2 = *(const float2*)(p + 8);
                float2 x3 = *(const float2*)(p + 8 * 36 + 8);
                ah[i][0] = pack2_hi(x0.x, x0.y); al[i][0] = pack2_lo(x0.x, x0.y, ah[i][0]);
                ah[i][1] = pack2_hi(x1.x, x1.y); al[i][1] = pack2_lo(x1.x, x1.y, ah[i][1]);
                ah[i][2] = pack2_hi(x2.x, x2.y); al[i][2] = pack2_lo(x2.x, x2.y, ah[i][2]);
                ah[i][3] = pack2_hi(x3.x, x3.y); al[i][3] = pack2_lo(x3.x, x3.y, ah[i][3]);
            }
            #pragma unroll
            for (int j = 0; j < 4; j++) {
                const uint32_t* p = bs + j * 8 * 36 + k0;
                unpk(*(const uint2*)(p),     bh[j][0], bl[j][0]);
                unpk(*(const uint2*)(p + 8), bh[j][1], bl[j][1]);
            }
            #pragma unroll
            for (int i = 0; i < 2; i++)
                #pragma unroll
                for (int j = 0; j < 4; j++) {
                    mma_bf16(acc[i][j], ah[i], bl[j]);
                    mma_bf16(acc[i][j], al[i], bh[j]);
                    mma_bf16(acc[i][j], ah[i], bh[j]);
                }
        }
        buf ^= 1;
    }

    const int m0 = row0 + wm * 32 + g;
    const int n0 = wn * 32 + 2 * q;
    #pragma unroll
    for (int i = 0; i < 2; i++)
        #pragma unroll
        for (int j = 0; j < 4; j++) {
            int c = n0 + j * 8;
            #pragma unroll
            for (int hh = 0; hh < 2; hh++) {
                int r = m0 + i * 16 + hh * 8;
                uint2* cp = (uint2*)(y + ((size_t)b*TT + r) * EE + h*HD + c);
                *cp = packpair(acc[i][j][hh*2+0], acc[i][j][hh*2+1]);
            }
        }
}

// ======================= merged weight prep ==================================
// blocks: [0,16000)        Wlm -> fp16 transpose
//         [16000,20096)    per-layer Wq/Wk/Wv/Wo transpose+pack
//         [20096,20352)    W1 padded transpose+pack
//         [20352,20608)    W2 padded transpose+pack
//         [20608,20612)    b1 pad
#define PREP_BLOCKS 20612
__global__ void prep_kernel(const float* __restrict__ Wq, const float* __restrict__ Wk,
                            const float* __restrict__ Wv, const float* __restrict__ Wo,
                            const float* __restrict__ W1, const float* __restrict__ b1,
                            const float* __restrict__ W2, const float* __restrict__ Wlm,
                            uint32_t* __restrict__ WT, uint32_t* __restrict__ W1Tp,
                            uint32_t* __restrict__ W2Tp, float* __restrict__ b1p,
                            __half* __restrict__ Wlm16) {
    __shared__ float t[32][33];
    int x = threadIdx.x, y = threadIdx.y;
    int bid = blockIdx.x;
    if (bid < 16000) {
        int nb = bid >> 4, kb = bid & 15;
        int n0 = nb * 32, k0 = kb * 32;
        #pragma unroll
        for (int j = 0; j < 32; j += 8)
            t[y + j][x] = Wlm[(size_t)(k0 + y + j) * VV + n0 + x];
        __syncthreads();
        #pragma unroll
        for (int j = 0; j < 32; j += 8)
            Wlm16[(size_t)(n0 + y + j) * EE + k0 + x] = __float2half(t[x][y + j]);
        return;
    }
    bid -= 16000;
    if (bid < 4096) {
        int p = bid >> 8, within = bid & 255;
        int l = p >> 2, w = p & 3;
        const float* W = (w == 0) ? Wq : (w == 1) ? Wk : (w == 2) ? Wv : Wo;
        W += (size_t)l * EE * EE;
        uint32_t* dst = WT + (size_t)l * 4 * EE * EE + (size_t)(w * 512) * EE;
        int nb = within >> 4, kb = within & 15;
        int n0 = nb * 32, k0 = kb * 32;
        #pragma unroll
        for (int j = 0; j < 32; j += 8)
            t[y + j][x] = W[(size_t)(k0 + y + j) * EE + n0 + x];
        __syncthreads();
        #pragma unroll
        for (int j = 0; j < 32; j += 8)
            dst[(size_t)(n0 + y + j) * EE + k0 + x] = packelem(t[x][y + j]);
        return;
    }
    bid -= 4096;
    if (bid < 256) {           // W1 [512,100] -> W1Tp [128,512]
        int l = bid >> 6, within = bid & 63;
        int nb = within >> 4, kb = within & 15;
        int n0 = nb * 32, k0 = kb * 32;
        const float* W = W1 + (size_t)l * EE * HIDN;
        uint32_t* dst = W1Tp + (size_t)l * HIDP * EE;
        #pragma unroll
        for (int j = 0; j < 32; j += 8) {
            int kk = k0 + y + j, nn = n0 + x;
            t[y + j][x] = (nn < HIDN) ? W[(size_t)kk * HIDN + nn] : 0.0f;
        }
        __syncthreads();
        #pragma unroll
        for (int j = 0; j < 32; j += 8)
            dst[(size_t)(n0 + y + j) * EE + k0 + x] = packelem(t[x][y + j]);
        return;
    }
    bid -= 256;
    if (bid < 256) {           // W2 [100,512] -> W2Tp [512,128]
        int l = bid >> 6, within = bid & 63;
        int nb = within >> 2, kb = within & 3;
        int n0 = nb * 32, k0 = kb * 32;
        const float* W = W2 + (size_t)l * HIDN * EE;
        uint32_t* dst = W2Tp + (size_t)l * EE * HIDP;
        #pragma unroll
        for (int j = 0; j < 32; j += 8) {
            int kk = k0 + y + j, nn = n0 + x;
            t[y + j][x] = (kk < HIDN) ? W[(size_t)kk * EE + nn] : 0.0f;
        }
        __syncthreads();
        #pragma unroll
        for (int j = 0; j < 32; j += 8)
            dst[(size_t)(n0 + y + j) * HIDP + k0 + x] = packelem(t[x][y + j]);
        return;
    }
    bid -= 256;                // b1 pad, bid = layer
    int tid = y * 32 + x;
    if (tid < HIDP) b1p[bid * HIDP + tid] = (tid < HIDN) ? b1[bid * HIDN + tid] : 0.0f;
}

// transpose packed V -> vT[b][e][s]
__global__ void vtrans_kernel(const uint32_t* __restrict__ qkv, uint32_t* __restrict__ vT) {
    __shared__ uint32_t t[32][33];
    int s0 = blockIdx.x * 32, e0 = blockIdx.y * 32, b = blockIdx.z;
    int x = threadIdx.x, y = threadIdx.y;
    #pragma unroll
    for (int j = 0; j < 32; j += 8)
        t[y + j][x] = qkv[((size_t)b*TT + s0 + y + j) * QKVS + 1024 + e0 + x];
    __syncthreads();
    #pragma unroll
    for (int j = 0; j < 32; j += 8)
        vT[((size_t)b*EE + e0 + y + j) * TT + s0 + x] = t[x][y + j];
}

// ---------------- embed ------------------------------------------------------
__global__ void embed_kernel(const int* __restrict__ idx,
                             const float* __restrict__ tok,
                             const float* __restrict__ pos,
                             float* __restrict__ x) {
    int row = blockIdx.x;
    int t = row & (TT - 1);
    int token = idx[row];
    const float4* tp = (const float4*)(tok + (size_t)token * EE);
    const float4* pp = (const float4*)(pos + (size_t)t * EE);
    float4* xp = (float4*)(x + (size_t)row * EE);
    int c = threadIdx.x;
    float4 a = tp[c], b = pp[c];
    xp[c] = make_float4(a.x + b.x, a.y + b.y, a.z + b.z, a.w + b.w);
}

// ---------------- layernorm -> packed output (bf16 or fp16) ------------------
template <bool F16>
__global__ void ln_kernel(const float* __restrict__ x, uint32_t* __restrict__ out,
                          const float* __restrict__ g, const float* __restrict__ b) {
    int row = blockIdx.x;
    int tid = threadIdx.x;
    const float4* xp = (const float4*)(x + (size_t)row * EE);
    float4 v = xp[tid];
    float s = v.x + v.y + v.z + v.w;
    __shared__ float red[4];
    for (int o = 16; o; o >>= 1) s += __shfl_xor_sync(~0u, s, o);
    if ((tid & 31) == 0) red[tid >> 5] = s;
    __syncthreads();
    float mean = (red[0] + red[1] + red[2] + red[3]) / (float)EE;
    float dx = v.x - mean, dy = v.y - mean, dz = v.z - mean, dw = v.w - mean;
    float ss = dx*dx + dy*dy + dz*dz + dw*dw;
    __syncthreads();
    for (int o = 16; o; o >>= 1) ss += __shfl_xor_sync(~0u, ss, o);
    if ((tid & 31) == 0) red[tid >> 5] = ss;
    __syncthreads();
    float var = (red[0] + red[1] + red[2] + red[3]) / (float)EE;
    float inv = 1.0f / sqrtf(var + 1e-5f);
    const float4* gp = (const float4*)g;
    const float4* bp = (const float4*)b;
    float4 gg = gp[tid], bb = bp[tid];
    float o0 = dx*inv*gg.x + bb.x, o1 = dy*inv*gg.y + bb.y;
    float o2 = dz*inv*gg.z + bb.z, o3 = dw*inv*gg.w + bb.w;
    uint2 p01 = F16 ? packpair16(o0, o1) : packpair(o0, o1);
    uint2 p23 = F16 ? packpair16(o2, o3) : packpair(o2, o3);
    uint4* op = (uint4*)(out + (size_t)row * EE);
    op[tid] = make_uint4(p01.x, p01.y, p23.x, p23.y);
}

// ---------------- causal softmax row -> writes attn map into d_out ----------
__global__ void softmax_kernel(const float* __restrict__ S, float* __restrict__ out) {
    int row = blockIdx.x;
    int t = row & (TT - 1);
    const float* sp = S + (size_t)row * TT;
    float* op = out + (size_t)row * TT;
    int tid = threadIdx.x;
    float vals[4];
    float m = -1e30f;
    #pragma unroll
    for (int i = 0; i < 4; i++) {
        int s = tid + i * 256;
        vals[i] = (s <= t) ? sp[s] : -1e30f;
        m = fmaxf(m, vals[i]);
    }
    __shared__ float red[8];
    for (int o = 16; o; o >>= 1) m = fmaxf(m, __shfl_xor_sync(~0u, m, o));
    if ((tid & 31) == 0) red[tid >> 5] = m;
    __syncthreads();
    m = red[0];
    #pragma unroll
    for (int i = 1; i < 8; i++) m = fmaxf(m, red[i]);
    float e[4];
    float ssum = 0.0f;
    #pragma unroll
    for (int i = 0; i < 4; i++) {
        int s = tid + i * 256;
        e[i] = (s <= t) ? expf(vals[i] - m) : 0.0f;
        ssum += e[i];
    }
    __syncthreads();
    for (int o = 16; o; o >>= 1) ssum += __shfl_xor_sync(~0u, ssum, o);
    if ((tid & 31) == 0) red[tid >> 5] = ssum;
    __syncthreads();
    float tot = 0.0f;
    #pragma unroll
    for (int i = 0; i < 8; i++) tot += red[i];
    float inv = 1.0f / tot;
    #pragma unroll
    for (int i = 0; i < 4; i++) {
        int s = tid + i * 256;
        op[s] = e[i] * inv;
    }
}

// ---------------- host orchestration ----------------------------------------
extern "C" void kernel_launch(void* const* d_in, const int* in_sizes, int n_in,
                              void* d_out, int out_size) {
    (void)in_sizes; (void)n_in; (void)out_size;
    const int*   idx     = (const int*)  d_in[0];
    const float* tok_emb = (const float*)d_in[1];
    const float* pos_emb = (const float*)d_in[2];
    const float* ln1_g   = (const float*)d_in[3];
    const float* ln1_b   = (const float*)d_in[4];
    const float* Wq      = (const float*)d_in[5];
    const float* Wk      = (const float*)d_in[6];
    const float* Wv      = (const float*)d_in[7];
    const float* Wo      = (const float*)d_in[8];
    const float* bo      = (const float*)d_in[9];
    const float* ln2_g   = (const float*)d_in[10];
    const float* ln2_b   = (const float*)d_in[11];
    const float* W1      = (const float*)d_in[12];
    const float* b1      = (const float*)d_in[13];
    const float* W2      = (const float*)d_in[14];
    const float* b2      = (const float*)d_in[15];
    const float* lnf_g   = (const float*)d_in[16];
    const float* lnf_b   = (const float*)d_in[17];
    const float* Wlm     = (const float*)d_in[18];

    float* out    = (float*)d_out;
    float* logits = out;
    float* attn   = out + LOGITS_N;

    float *gx, *gS, *gb1p;
    uint32_t *gh, *gqkv, *gy, *gu, *gvT, *gWT, *gW1Tp, *gW2Tp;
    __half *gWlm16;
    cudaGetSymbolAddress((void**)&gx, d_x);
    cudaGetSymbolAddress((void**)&gh, d_h);
    cudaGetSymbolAddress((void**)&gqkv, d_qkv);
    cudaGetSymbolAddress((void**)&gy, d_y);
    cudaGetSymbolAddress((void**)&gu, d_u);
    cudaGetSymbolAddress((void**)&gS, d_S);
    cudaGetSymbolAddress((void**)&gvT, d_vT);
    cudaGetSymbolAddress((void**)&gWlm16, d_Wlm16);
    cudaGetSymbolAddress((void**)&gWT, d_WT);
    cudaGetSymbolAddress((void**)&gW1Tp, d_W1Tp);
    cudaGetSymbolAddress((void**)&gW2Tp, d_W2Tp);
    cudaGetSymbolAddress((void**)&gb1p, d_b1p);

    cudaFuncSetAttribute(mma_gemm<false,false,false,true>,
                         cudaFuncAttributeMaxDynamicSharedMemorySize, GEMM_SMEM);
    cudaFuncSetAttribute(mma_gemm<true,true,false,false>,
                         cudaFuncAttributeMaxDynamicSharedMemorySize, GEMM_SMEM);
    cudaFuncSetAttribute(mma_gemm<true,false,true,true>,
                         cudaFuncAttributeMaxDynamicSharedMemorySize, GEMM_SMEM);
    cudaFuncSetAttribute(qk_mma, cudaFuncAttributeMaxDynamicSharedMemorySize, GEMM_SMEM);
    cudaFuncSetAttribute(av_mma, cudaFuncAttributeMaxDynamicSharedMemorySize, AV_SMEM);
    cudaFuncSetAttribute(lm_gemm, cudaFuncAttributeMaxDynamicSharedMemorySize, LM_SMEM);

    // one merged weight-prep launch
    prep_kernel<<<PREP_BLOCKS, dim3(32, 8)>>>(Wq, Wk, Wv, Wo, W1, b1, W2, Wlm,
                                              gWT, gW1Tp, gW2Tp, gb1p, gWlm16);

    embed_kernel<<<BT, 128>>>(idx, tok_emb, pos_emb, gx);

    for (int l = 0; l < LL; l++) {
        uint32_t* base = gWT + (size_t)l * 4 * EE * EE;
        const uint32_t* qkvT = base;
        const uint32_t* woT  = base + (size_t)1536*EE;
        float* attn_l = attn + (size_t)l * ATT_PER_L;

        ln_kernel<false><<<BT, 128>>>(gx, gh, ln1_g + l*EE, ln1_b + l*EE);

        // fused QKV (packed in, packed out)
        mma_gemm<false,false,false,true><<<dim3(QKVS/128, BT/128), 256, GEMM_SMEM>>>(
            gh, qkvT, nullptr, nullptr, (float*)gqkv, BT, QKVS, EE);

        qk_mma<<<dim3(8, 8, BB*HH), 256, GEMM_SMEM>>>(gqkv, gS);
        softmax_kernel<<<BHT, 256>>>(gS, attn_l);
        vtrans_kernel<<<dim3(TT/32, EE/32, BB), dim3(32, 8)>>>(gqkv, gvT);
        av_mma<<<dim3(8, 1, BB*HH), 256, AV_SMEM>>>(attn_l, gvT, gy);

        // x = x + y @ Wo + bo
        mma_gemm<true,true,false,false><<<dim3(EE/128, BT/128), 256, GEMM_SMEM>>>(
            gy, woT, bo + l*EE, gx, gx, BT, EE, EE);

        ln_kernel<false><<<BT, 128>>>(gx, gh, ln2_g + l*EE, ln2_b + l*EE);

        // u = relu(h @ W1 + b1)
        mma_gemm<true,false,true,true><<<dim3(HIDP/128, BT/128), 256, GEMM_SMEM>>>(
            gh, gW1Tp + (size_t)l*HIDP*EE, gb1p + l*HIDP, nullptr, (float*)gu, BT, HIDP, EE);
        // x = x + u @ W2 + b2
        mma_gemm<true,true,false,false><<<dim3(EE/128, BT/128), 256, GEMM_SMEM>>>(
            gu, gW2Tp + (size_t)l*EE*HIDP, b2 + l*EE, gx, gx, BT, EE, HIDP);
    }

    // final LN packs fp16 pairs for the fp16 logits GEMM
    ln_kernel<true><<<BT, 128>>>(gx, gh, lnf_g, lnf_b);
    lm_gemm<<<dim3(BT/128, VV/128), 256, LM_SMEM>>>(gh, gWlm16, logits, BT, VV, EE);
}

// round 16
// speedup vs baseline: 1.2497x; 1.0262x over previous
#include <cuda_runtime.h>
#include <cuda_bf16.h>
#include <cuda_fp16.h>
#include <cstdint>
#include <cstddef>

// Problem dims
#define BB 4
#define TT 1024
#define EE 512
#define HH 8
#define LL 4
#define VV 32000
#define HIDN 100
#define HIDP 128
#define HD 64
#define BT (BB*TT)          // 4096
#define BHT (BB*HH*TT)      // 32768
#define QKVS 1536           // packed qkv row stride
#define ATT_PER_L ((size_t)BB*HH*TT*TT)
#define LOGITS_N ((size_t)BT*VV)

// ---------------- scratch (device globals; no allocations allowed) ----------
// Packed format: uint32 = 16_hi(f) | 16_lo(f - hi) << 16   (bf16 or fp16)
__device__ float    d_x[BT*EE];                   // residual stream (fp32)
__device__ uint32_t d_h[BT*EE];                   // packed LN output
__device__ uint32_t d_qkv[(size_t)BT*QKVS];       // packed q,k,v
__device__ uint32_t d_y[BT*EE];                   // packed attn output
__device__ uint32_t d_u[BT*HIDP];                 // packed ffn hidden
__device__ float    d_S[(size_t)BB*HH*TT*TT];     // raw scores fp32, 128 MB
__device__ uint32_t d_vT[(size_t)BB*EE*TT];       // packed V^T [b][e][s]
__device__ __half   d_Wlm16[(size_t)VV*EE];       // Wlm^T as fp16 [V,E]
__device__ uint32_t d_WT[(size_t)LL*4*EE*EE];     // packed per-layer qkvT+woT
__device__ uint32_t d_W1Tp[(size_t)LL*HIDP*EE];   // packed padded W1^T
__device__ uint32_t d_W2Tp[(size_t)LL*EE*HIDP];   // packed padded W2^T
__device__ float    d_b1p[LL*HIDP];

// ======================= helpers =============================================
#define TILE_F (128*36)           // elems per smem tile (padded rows)
#define GEMM_SMEM (4*TILE_F*4)
#define AV_SMEM  (2*(128*36 + 64*36)*4)
// logits kernel smem: A 2x(128*36 words), B 2x(128*40 halfs)
#define LMPAD 40
#define LM_AS (128*36)
#define LM_BS (128*LMPAD)
#define LM_SMEM (2*LM_AS*4 + 2*LM_BS*2)

__device__ __forceinline__ uint32_t smem_u32(const void* p) {
    uint32_t a;
    asm("{ .reg .u64 t; cvta.to.shared.u64 t, %1; cvt.u32.u64 %0, t; }"
        : "=r"(a) : "l"(p));
    return a;
}
__device__ __forceinline__ void cp16(uint32_t saddr, const void* g) {
    asm volatile("cp.async.cg.shared.global [%0], [%1], 16;" :: "r"(saddr), "l"(g));
}
__device__ __forceinline__ uint32_t pack2_hi(float f0, float f1) {
    uint32_t r;
    asm("cvt.rn.bf16x2.f32 %0, %1, %2;" : "=r"(r) : "f"(f1), "f"(f0));
    return r;
}
__device__ __forceinline__ uint32_t pack2_lo(float f0, float f1, uint32_t hi) {
    float h0 = __uint_as_float(hi << 16);
    float h1 = __uint_as_float(hi & 0xffff0000u);
    uint32_t r;
    asm("cvt.rn.bf16x2.f32 %0, %1, %2;" : "=r"(r) : "f"(f1 - h1), "f"(f0 - h0));
    return r;
}
__device__ __forceinline__ uint32_t packelem(float f) {
    uint32_t H = pack2_hi(f, 0.0f);
    float hf = __uint_as_float(H << 16);
    uint32_t L = pack2_hi(f - hf, 0.0f);
    return (H & 0xffffu) | (L << 16);
}
__device__ __forceinline__ uint2 packpair(float f0, float f1) {
    uint32_t H = pack2_hi(f0, f1);
    uint32_t L = pack2_lo(f0, f1, H);
    return make_uint2(__byte_perm(H, L, 0x5410), __byte_perm(H, L, 0x7632));
}
// fp16 pair pack: per element word = f16_hi | f16_lo<<16
__device__ __forceinline__ uint2 packpair16(float f0, float f1) {
    uint32_t H;
    asm("cvt.rn.f16x2.f32 %0, %1, %2;" : "=r"(H) : "f"(f1), "f"(f0));
    float h0, h1;
    asm("{.reg .b16 a,b;\n\t mov.b32 {a,b}, %2;\n\t cvt.f32.f16 %0, a;\n\t cvt.f32.f16 %1, b;}"
        : "=f"(h0), "=f"(h1) : "r"(H));
    uint32_t L;
    asm("cvt.rn.f16x2.f32 %0, %1, %2;" : "=r"(L) : "f"(f1 - h1), "f"(f0 - h0));
    return make_uint2(__byte_perm(H, L, 0x5410), __byte_perm(H, L, 0x7632));
}
__device__ __forceinline__ void unpk(uint2 w, uint32_t& hi, uint32_t& lo) {
    hi = __byte_perm(w.x, w.y, 0x5410);
    lo = __byte_perm(w.x, w.y, 0x7632);
}
// hi-plane only (for 1-term logits)
__device__ __forceinline__ uint32_t unpk_hi(uint2 w) {
    return __byte_perm(w.x, w.y, 0x5410);
}
__device__ __forceinline__ void mma_bf16(float c[4], const uint32_t a[4], const uint32_t b[2]) {
    asm volatile(
        "mma.sync.aligned.m16n8k16.row.col.f32.bf16.bf16.f32 "
        "{%0,%1,%2,%3}, {%4,%5,%6,%7}, {%8,%9}, {%0,%1,%2,%3};"
        : "+f"(c[0]), "+f"(c[1]), "+f"(c[2]), "+f"(c[3])
        : "r"(a[0]), "r"(a[1]), "r"(a[2]), "r"(a[3]), "r"(b[0]), "r"(b[1]));
}
__device__ __forceinline__ void mma_f16(float c[4], const uint32_t a[4], const uint32_t b[2]) {
    asm volatile(
        "mma.sync.aligned.m16n8k16.row.col.f32.f16.f16.f32 "
        "{%0,%1,%2,%3}, {%4,%5,%6,%7}, {%8,%9}, {%0,%1,%2,%3};"
        : "+f"(c[0]), "+f"(c[1]), "+f"(c[2]), "+f"(c[3])
        : "r"(a[0]), "r"(a[1]), "r"(a[2]), "r"(a[3]), "r"(b[0]), "r"(b[1]));
}

// ======================= packed bf16 mma GEMM (3-term) =======================
template <bool BIAS, bool RES, bool RELU, bool PACKOUT>
__global__ void __launch_bounds__(256, 2)
mma_gemm(const uint32_t* __restrict__ A, const uint32_t* __restrict__ BT_,
         const float* __restrict__ bias, const float* __restrict__ res,
         float* __restrict__ C, int M, int N, int K) {
    extern __shared__ float smem_f[];
    uint32_t* As = (uint32_t*)smem_f;
    uint32_t* Bs = (uint32_t*)smem_f + 2*TILE_F;

    const int tid = threadIdx.x;
    const int wid = tid >> 5;
    const int lane = tid & 31;
    const int g = lane >> 2, q = lane & 3;
    const int wm = wid & 1, wn = wid >> 1;

    const int row0 = blockIdx.y * 128;
    const int col0 = blockIdx.x * 128;
    const uint32_t* Ap = A + (size_t)row0 * K;
    const uint32_t* Bp = BT_ + (size_t)col0 * K;

    const uint32_t sA0 = smem_u32(As);
    const uint32_t sB0 = smem_u32(Bs);

    const int NK = K >> 5;

    int lrow[4], lc4[4];
    #pragma unroll
    for (int j = 0; j < 4; j++) {
        int i = tid + j * 256;
        lrow[j] = i >> 3;
        lc4[j] = i & 7;
    }

    auto load_stage = [&](int buf, int kt) {
        const int k0 = kt << 5;
        const uint32_t offA = sA0 + buf * TILE_F * 4;
        const uint32_t offB = sB0 + buf * TILE_F * 4;
        #pragma unroll
        for (int j = 0; j < 4; j++) {
            uint32_t so = (uint32_t)(lrow[j] * 36 + lc4[j] * 4) * 4;
            cp16(offA + so, Ap + (size_t)lrow[j] * K + k0 + lc4[j] * 4);
            cp16(offB + so, Bp + (size_t)lrow[j] * K + k0 + lc4[j] * 4);
        }
        asm volatile("cp.async.commit_group;");
    };

    float acc[4][4][4];
    #pragma unroll
    for (int i = 0; i < 4; i++)
        #pragma unroll
        for (int j = 0; j < 4; j++)
            #pragma unroll
            for (int t = 0; t < 4; t++) acc[i][j][t] = 0.0f;

    load_stage(0, 0);

    int buf = 0;
    for (int kt = 0; kt < NK; kt++) {
        asm volatile("cp.async.wait_group 0;");
        __syncthreads();
        if (kt + 1 < NK) load_stage(buf ^ 1, kt + 1);

        const uint32_t* as = As + buf * TILE_F + (wm * 64 + g) * 36 + 2 * q;
        const uint32_t* bs = Bs + buf * TILE_F + (wn * 32 + g) * 36 + 2 * q;
        #pragma unroll
        for (int s = 0; s < 2; s++) {
            const int k0 = s * 16;
            uint32_t ah[4][4], al[4][4], bh[4][2], bl[4][2];
            #pragma unroll
            for (int i = 0; i < 4; i++) {
                const uint32_t* p = as + i * 16 * 36 + k0;
                unpk(*(const uint2*)(p),              ah[i][0], al[i][0]);
                unpk(*(const uint2*)(p + 8 * 36),     ah[i][1], al[i][1]);
                unpk(*(const uint2*)(p + 8),          ah[i][2], al[i][2]);
                unpk(*(const uint2*)(p + 8 * 36 + 8), ah[i][3], al[i][3]);
            }
            #pragma unroll
            for (int j = 0; j < 4; j++) {
                const uint32_t* p = bs + j * 8 * 36 + k0;
                unpk(*(const uint2*)(p),     bh[j][0], bl[j][0]);
                unpk(*(const uint2*)(p + 8), bh[j][1], bl[j][1]);
            }
            #pragma unroll
            for (int i = 0; i < 4; i++)
                #pragma unroll
                for (int j = 0; j < 4; j++) {
                    mma_bf16(acc[i][j], ah[i], bl[j]);
                    mma_bf16(acc[i][j], al[i], bh[j]);
                    mma_bf16(acc[i][j], ah[i], bh[j]);
                }
        }
        buf ^= 1;
    }

    const int m0 = row0 + wm * 64 + g;
    const int n0 = col0 + wn * 32 + 2 * q;
    #pragma unroll
    for (int i = 0; i < 4; i++) {
        #pragma unroll
        for (int j = 0; j < 4; j++) {
            int c = n0 + j * 8;
            float b0 = 0.f, b1 = 0.f;
            if (BIAS) { b0 = bias[c]; b1 = bias[c + 1]; }
            #pragma unroll
            for (int hh = 0; hh < 2; hh++) {
                int r = m0 + i * 16 + hh * 8;
                float v0 = acc[i][j][hh * 2 + 0] + b0;
                float v1 = acc[i][j][hh * 2 + 1] + b1;
                if (RES) {
                    const float* rp = res + (size_t)r * N + c;
                    v0 += rp[0]; v1 += rp[1];
                }
                if (RELU) { v0 = fmaxf(v0, 0.f); v1 = fmaxf(v1, 0.f); }
                if (PACKOUT) {
                    uint2* cp = (uint2*)((uint32_t*)C + (size_t)r * N + c);
                    *cp = packpair(v0, v1);
                } else {
                    float2* cp = (float2*)(C + (size_t)r * N + c);
                    *cp = make_float2(v0, v1);
                }
            }
        }
    }
}

// ======================= logits GEMM: fp16 1-term ============================
// C[M,N] = A[M,K] @ Wlm; A packed fp16-pair uint32 (hi plane used), B fp16 [N,K].
// M-fastest grid for L2-friendly weight streaming.
__global__ void __launch_bounds__(256, 2)
lm_gemm(const uint32_t* __restrict__ A, const __half* __restrict__ BT_,
        float* __restrict__ C, int M, int N, int K) {
    extern __shared__ float smem_f[];
    uint32_t* As = (uint32_t*)smem_f;                       // 2*LM_AS words
    uint32_t* Bs = (uint32_t*)smem_f + 2*LM_AS;             // 2*LM_BS halfs

    const int tid = threadIdx.x;
    const int wid = tid >> 5;
    const int lane = tid & 31;
    const int g = lane >> 2, q = lane & 3;
    const int wm = wid & 1, wn = wid >> 1;

    const int row0 = blockIdx.x * 128;      // M-fastest
    const int col0 = blockIdx.y * 128;
    const uint32_t* Ap = A + (size_t)row0 * K;
    const __half* Bp = BT_ + (size_t)col0 * K;

    const uint32_t sA0 = smem_u32(As);
    const uint32_t sB0 = smem_u32(Bs);

    const int NK = K >> 5;                  // 16

    int lrow[4], lc4[4];
    #pragma unroll
    for (int j = 0; j < 4; j++) {
        int i = tid + j * 256;
        lrow[j] = i >> 3;
        lc4[j] = i & 7;
    }
    int brow[2], bc4[2];
    #pragma unroll
    for (int j = 0; j < 2; j++) {
        int i = tid + j * 256;
        brow[j] = i >> 2;
        bc4[j] = i & 3;
    }

    auto load_stage = [&](int buf, int kt) {
        const int k0 = kt << 5;
        const uint32_t offA = sA0 + buf * LM_AS * 4;
        const uint32_t offB = sB0 + buf * LM_BS * 2;
        #pragma unroll
        for (int j = 0; j < 4; j++) {
            uint32_t so = (uint32_t)(lrow[j] * 36 + lc4[j] * 4) * 4;
            cp16(offA + so, Ap + (size_t)lrow[j] * K + k0 + lc4[j] * 4);
        }
        #pragma unroll
        for (int j = 0; j < 2; j++) {
            uint32_t so = (uint32_t)(brow[j] * 80 + bc4[j] * 16);
            cp16(offB + so, Bp + (size_t)brow[j] * K + k0 + bc4[j] * 8);
        }
        asm volatile("cp.async.commit_group;");
    };

    float acc[4][4][4];
    #pragma unroll
    for (int i = 0; i < 4; i++)
        #pragma unroll
        for (int j = 0; j < 4; j++)
            #pragma unroll
            for (int t = 0; t < 4; t++) acc[i][j][t] = 0.0f;

    load_stage(0, 0);

    int buf = 0;
    for (int kt = 0; kt < NK; kt++) {
        asm volatile("cp.async.wait_group 0;");
        __syncthreads();
        if (kt + 1 < NK) load_stage(buf ^ 1, kt + 1);

        const uint32_t* as = As + buf * LM_AS + (wm * 64 + g) * 36 + 2 * q;
        const uint32_t* bsw = Bs + buf * (LM_BS / 2) + (wn * 32 + g) * (LMPAD / 2);
        #pragma unroll
        for (int s = 0; s < 2; s++) {
            const int k0 = s * 16;
            uint32_t ah[4][4], bh[4][2];
            #pragma unroll
            for (int i = 0; i < 4; i++) {
                const uint32_t* p = as + i * 16 * 36 + k0;
                ah[i][0] = unpk_hi(*(const uint2*)(p));
                ah[i][1] = unpk_hi(*(const uint2*)(p + 8 * 36));
                ah[i][2] = unpk_hi(*(const uint2*)(p + 8));
                ah[i][3] = unpk_hi(*(const uint2*)(p + 8 * 36 + 8));
            }
            #pragma unroll
            for (int j = 0; j < 4; j++) {
                const uint32_t* p = bsw + j * 8 * (LMPAD / 2) + s * 8 + q;
                bh[j][0] = p[0];
                bh[j][1] = p[4];
            }
            #pragma unroll
            for (int i = 0; i < 4; i++)
                #pragma unroll
                for (int j = 0; j < 4; j++)
                    mma_f16(acc[i][j], ah[i], bh[j]);
        }
        buf ^= 1;
    }

    const int m0 = row0 + wm * 64 + g;
    const int n0 = col0 + wn * 32 + 2 * q;
    #pragma unroll
    for (int i = 0; i < 4; i++)
        #pragma unroll
        for (int j = 0; j < 4; j++) {
            int c = n0 + j * 8;
            #pragma unroll
            for (int hh = 0; hh < 2; hh++) {
                int r = m0 + i * 16 + hh * 8;
                float2* cp = (float2*)(C + (size_t)r * N + c);
                *cp = make_float2(acc[i][j][hh * 2 + 0], acc[i][j][hh * 2 + 1]);
            }
        }
}

// ======================= QK^T via packed bf16 mma ============================
__global__ void __launch_bounds__(256, 2)
qk_mma(const uint32_t* __restrict__ qkv, float* __restrict__ S) {
    if (blockIdx.x > blockIdx.y) return;
    extern __shared__ float smem_f[];
    uint32_t* As = (uint32_t*)smem_f;
    uint32_t* Bs = (uint32_t*)smem_f + 2*TILE_F;

    const int tid = threadIdx.x;
    const int wid = tid >> 5;
    const int lane = tid & 31;
    const int g = lane >> 2, q = lane & 3;
    const int wm = wid & 1, wn = wid >> 1;

    const int row0 = blockIdx.y * 128;
    const int col0 = blockIdx.x * 128;
    const int b = blockIdx.z >> 3, h = blockIdx.z & 7;
    const uint32_t* Ap = qkv + ((size_t)b*TT + row0) * QKVS + h*HD;
    const uint32_t* Bp = qkv + 512 + ((size_t)b*TT + col0) * QKVS + h*HD;

    const uint32_t sA0 = smem_u32(As);
    const uint32_t sB0 = smem_u32(Bs);

    int lrow[4], lc4[4];
    #pragma unroll
    for (int j = 0; j < 4; j++) {
        int i = tid + j * 256;
        lrow[j] = i >> 3;
        lc4[j] = i & 7;
    }

    auto load_stage = [&](int buf, int kt) {
        const int k0 = kt << 5;
        const uint32_t offA = sA0 + buf * TILE_F * 4;
        const uint32_t offB = sB0 + buf * TILE_F * 4;
        #pragma unroll
        for (int j = 0; j < 4; j++) {
            uint32_t so = (uint32_t)(lrow[j] * 36 + lc4[j] * 4) * 4;
            cp16(offA + so, Ap + (size_t)lrow[j] * QKVS + k0 + lc4[j] * 4);
            cp16(offB + so, Bp + (size_t)lrow[j] * QKVS + k0 + lc4[j] * 4);
        }
        asm volatile("cp.async.commit_group;");
    };

    float acc[4][4][4];
    #pragma unroll
    for (int i = 0; i < 4; i++)
        #pragma unroll
        for (int j = 0; j < 4; j++)
            #pragma unroll
            for (int t = 0; t < 4; t++) acc[i][j][t] = 0.0f;

    load_stage(0, 0);

    int buf = 0;
    for (int kt = 0; kt < 2; kt++) {
        asm volatile("cp.async.wait_group 0;");
        __syncthreads();
        if (kt == 0) load_stage(1, 1);

        const uint32_t* as = As + buf * TILE_F + (wm * 64 + g) * 36 + 2 * q;
        const uint32_t* bs = Bs + buf * TILE_F + (wn * 32 + g) * 36 + 2 * q;
        #pragma unroll
        for (int s = 0; s < 2; s++) {
            const int k0 = s * 16;
            uint32_t ah[4][4], al[4][4], bh[4][2], bl[4][2];
            #pragma unroll
            for (int i = 0; i < 4; i++) {
                const uint32_t* p = as + i * 16 * 36 + k0;
                unpk(*(const uint2*)(p),              ah[i][0], al[i][0]);
                unpk(*(const uint2*)(p + 8 * 36),     ah[i][1], al[i][1]);
                unpk(*(const uint2*)(p + 8),          ah[i][2], al[i][2]);
                unpk(*(const uint2*)(p + 8 * 36 + 8), ah[i][3], al[i][3]);
            }
            #pragma unroll
            for (int j = 0; j < 4; j++) {
                const uint32_t* p = bs + j * 8 * 36 + k0;
                unpk(*(const uint2*)(p),     bh[j][0], bl[j][0]);
                unpk(*(const uint2*)(p + 8), bh[j][1], bl[j][1]);
            }
            #pragma unroll
            for (int i = 0; i < 4; i++)
                #pragma unroll
                for (int j = 0; j < 4; j++) {
                    mma_bf16(acc[i][j], ah[i], bl[j]);
                    mma_bf16(acc[i][j], al[i], bh[j]);
                    mma_bf16(acc[i][j], ah[i], bh[j]);
                }
        }
        buf ^= 1;
    }

    float* Sp = S + (size_t)blockIdx.z * TT * TT;
    const int m0 = row0 + wm * 64 + g;
    const int n0 = col0 + wn * 32 + 2 * q;
    #pragma unroll
    for (int i = 0; i < 4; i++)
        #pragma unroll
        for (int j = 0; j < 4; j++) {
            int c = n0 + j * 8;
            #pragma unroll
            for (int hh = 0; hh < 2; hh++) {
                int r = m0 + i * 16 + hh * 8;
                float2* cp = (float2*)(Sp + (size_t)r * TT + c);
                *cp = make_float2(acc[i][j][hh*2+0] * 0.125f, acc[i][j][hh*2+1] * 0.125f);
            }
        }
}

// ======================= P @ V via bf16 mma ==================================
#define AV_AF (128*36)
#define AV_BF (64*36)
__global__ void __launch_bounds__(256, 2)
av_mma(const float* __restrict__ P, const uint32_t* __restrict__ vT,
       uint32_t* __restrict__ y) {
    extern __shared__ float smem_f[];
    float* As = smem_f;
    uint32_t* Bs = (uint32_t*)smem_f + 2*AV_AF;

    const int tid = threadIdx.x;
    const int wid = tid >> 5;
    const int lane = tid & 31;
    const int g = lane >> 2, q = lane & 3;
    const int wm = wid & 3, wn = wid >> 2;

    const int row0 = blockIdx.x * 128;
    const int b = blockIdx.z >> 3, h = blockIdx.z & 7;
    const float* Ap = P + (size_t)blockIdx.z * TT * TT + (size_t)row0 * TT;
    const uint32_t* Bp = vT + ((size_t)b*EE + h*HD) * TT;

    const uint32_t sA0 = smem_u32(As);
    const uint32_t sB0 = smem_u32(Bs);

    const int NK = (row0 >> 5) + 4;

    int arow[4], ac4[4], brow[2], bc4[2];
    #pragma unroll
    for (int j = 0; j < 4; j++) {
        int i = tid + j * 256;
        arow[j] = i >> 3; ac4[j] = i & 7;
    }
    #pragma unroll
    for (int j = 0; j < 2; j++) {
        int i = tid + j * 256;
        brow[j] = i >> 3; bc4[j] = i & 7;
    }

    auto load_stage = [&](int buf, int kt) {
        const int k0 = kt << 5;
        const uint32_t offA = sA0 + buf * AV_AF * 4;
        const uint32_t offB = sB0 + buf * AV_BF * 4;
        #pragma unroll
        for (int j = 0; j < 4; j++) {
            uint32_t so = (uint32_t)(arow[j] * 36 + ac4[j] * 4) * 4;
            cp16(offA + so, Ap + (size_t)arow[j] * TT + k0 + ac4[j] * 4);
        }
        #pragma unroll
        for (int j = 0; j < 2; j++) {
            uint32_t so = (uint32_t)(brow[j] * 36 + bc4[j] * 4) * 4;
            cp16(offB + so, Bp + (size_t)brow[j] * TT + k0 + bc4[j] * 4);
        }
        asm volatile("cp.async.commit_group;");
    };

    float acc[2][4][4];
    #pragma unroll
    for (int i = 0; i < 2; i++)
        #pragma unroll
        for (int j = 0; j < 4; j++)
            #pragma unroll
            for (int t = 0; t < 4; t++) acc[i][j][t] = 0.0f;

    load_stage(0, 0);

    int buf = 0;
    for (int kt = 0; kt < NK; kt++) {
        asm volatile("cp.async.wait_group 0;");
        __syncthreads();
        if (kt + 1 < NK) load_stage(buf ^ 1, kt + 1);

        const float* as = As + buf * AV_AF + (wm * 32 + g) * 36 + 2 * q;
        const uint32_t* bs = Bs + buf * AV_BF + (wn * 32 + g) * 36 + 2 * q;
        #pragma unroll
        for (int s = 0; s < 2; s++) {
            const int k0 = s * 16;
            uint32_t ah[2][4], al[2][4], bh[4][2], bl[4][2];
            #pragma unroll
            for (int i = 0; i < 2; i++) {
                const float* p = as + i * 16 * 36 + k0;
                float2 x0 = *(const float2*)(p);
                float2 x1 = *(const float2*)(p + 8 * 36);
                float2 x2 = *(const float2*)(p + 8);
                float2 x3 = *(const float2*)(p + 8 * 36 + 8);
                ah[i][0] = pack2_hi(x0.x, x0.y); al[i][0] = pack2_lo(x0.x, x0.y, ah[i][0]);
                ah[i][1] = pack2_hi(x1.x, x1.y); al[i][1] = pack2_lo(x1.x, x1.y, ah[i][1]);
                ah[i][2] = pack2_hi(x2.x, x2.y); al[i][2] = pack2_lo(x2.x, x2.y, ah[i][2]);
                ah[i][3] = pack2_hi(x3.x, x3.y); al[i][3] = pack2_lo(x3.x, x3.y, ah[i][3]);
            }
            #pragma unroll
            for (int j = 0; j < 4; j++) {
                const uint32_t* p = bs + j * 8 * 36 + k0;
                unpk(*(const uint2*)(p),     bh[j][0], bl[j][0]);
                unpk(*(const uint2*)(p + 8), bh[j][1], bl[j][1]);
            }
            #pragma unroll
            for (int i = 0; i < 2; i++)
                #pragma unroll
                for (int j = 0; j < 4; j++) {
                    mma_bf16(acc[i][j], ah[i], bl[j]);
                    mma_bf16(acc[i][j], al[i], bh[j]);
                    mma_bf16(acc[i][j], ah[i], bh[j]);
                }
        }
        buf ^= 1;
    }

    const int m0 = row0 + wm * 32 + g;
    const int n0 = wn * 32 + 2 * q;
    #pragma unroll
    for (int i = 0; i < 2; i++)
        #pragma unroll
        for (int j = 0; j < 4; j++) {
            int c = n0 + j * 8;
            #pragma unroll
            for (int hh = 0; hh < 2; hh++) {
                int r = m0 + i * 16 + hh * 8;
                uint2* cp = (uint2*)(y + ((size_t)b*TT + r) * EE + h*HD + c);
                *cp = packpair(acc[i][j][hh*2+0], acc[i][j][hh*2+1]);
            }
        }
}

// ======================= merged weight prep ==================================
#define PREP_BLOCKS 20612
__global__ void prep_kernel(const float* __restrict__ Wq, const float* __restrict__ Wk,
                            const float* __restrict__ Wv, const float* __restrict__ Wo,
                            const float* __restrict__ W1, const float* __restrict__ b1,
                            const float* __restrict__ W2, const float* __restrict__ Wlm,
                            uint32_t* __restrict__ WT, uint32_t* __restrict__ W1Tp,
                            uint32_t* __restrict__ W2Tp, float* __restrict__ b1p,
                            __half* __restrict__ Wlm16) {
    __shared__ float t[32][33];
    int x = threadIdx.x, y = threadIdx.y;
    int bid = blockIdx.x;
    if (bid < 16000) {
        int nb = bid >> 4, kb = bid & 15;
        int n0 = nb * 32, k0 = kb * 32;
        #pragma unroll
        for (int j = 0; j < 32; j += 8)
            t[y + j][x] = Wlm[(size_t)(k0 + y + j) * VV + n0 + x];
        __syncthreads();
        #pragma unroll
        for (int j = 0; j < 32; j += 8)
            Wlm16[(size_t)(n0 + y + j) * EE + k0 + x] = __float2half(t[x][y + j]);
        return;
    }
    bid -= 16000;
    if (bid < 4096) {
        int p = bid >> 8, within = bid & 255;
        int l = p >> 2, w = p & 3;
        const float* W = (w == 0) ? Wq : (w == 1) ? Wk : (w == 2) ? Wv : Wo;
        W += (size_t)l * EE * EE;
        uint32_t* dst = WT + (size_t)l * 4 * EE * EE + (size_t)(w * 512) * EE;
        int nb = within >> 4, kb = within & 15;
        int n0 = nb * 32, k0 = kb * 32;
        #pragma unroll
        for (int j = 0; j < 32; j += 8)
            t[y + j][x] = W[(size_t)(k0 + y + j) * EE + n0 + x];
        __syncthreads();
        #pragma unroll
        for (int j = 0; j < 32; j += 8)
            dst[(size_t)(n0 + y + j) * EE + k0 + x] = packelem(t[x][y + j]);
        return;
    }
    bid -= 4096;
    if (bid < 256) {           // W1 [512,100] -> W1Tp [128,512]
        int l = bid >> 6, within = bid & 63;
        int nb = within >> 4, kb = within & 15;
        int n0 = nb * 32, k0 = kb * 32;
        const float* W = W1 + (size_t)l * EE * HIDN;
        uint32_t* dst = W1Tp + (size_t)l * HIDP * EE;
        #pragma unroll
        for (int j = 0; j < 32; j += 8) {
            int kk = k0 + y + j, nn = n0 + x;
            t[y + j][x] = (nn < HIDN) ? W[(size_t)kk * HIDN + nn] : 0.0f;
        }
        __syncthreads();
        #pragma unroll
        for (int j = 0; j < 32; j += 8)
            dst[(size_t)(n0 + y + j) * EE + k0 + x] = packelem(t[x][y + j]);
        return;
    }
    bid -= 256;
    if (bid < 256) {           // W2 [100,512] -> W2Tp [512,128]
        int l = bid >> 6, within = bid & 63;
        int nb = within >> 2, kb = within & 3;
        int n0 = nb * 32, k0 = kb * 32;
        const float* W = W2 + (size_t)l * HIDN * EE;
        uint32_t* dst = W2Tp + (size_t)l * EE * HIDP;
        #pragma unroll
        for (int j = 0; j < 32; j += 8) {
            int kk = k0 + y + j, nn = n0 + x;
            t[y + j][x] = (kk < HIDN) ? W[(size_t)kk * EE + nn] : 0.0f;
        }
        __syncthreads();
        #pragma unroll
        for (int j = 0; j < 32; j += 8)
            dst[(size_t)(n0 + y + j) * HIDP + k0 + x] = packelem(t[x][y + j]);
        return;
    }
    bid -= 256;                // b1 pad, bid = layer
    int tid = y * 32 + x;
    if (tid < HIDP) b1p[bid * HIDP + tid] = (tid < HIDN) ? b1[bid * HIDN + tid] : 0.0f;
}

// transpose packed V -> vT[b][e][s]
__global__ void vtrans_kernel(const uint32_t* __restrict__ qkv, uint32_t* __restrict__ vT) {
    __shared__ uint32_t t[32][33];
    int s0 = blockIdx.x * 32, e0 = blockIdx.y * 32, b = blockIdx.z;
    int x = threadIdx.x, y = threadIdx.y;
    #pragma unroll
    for (int j = 0; j < 32; j += 8)
        t[y + j][x] = qkv[((size_t)b*TT + s0 + y + j) * QKVS + 1024 + e0 + x];
    __syncthreads();
    #pragma unroll
    for (int j = 0; j < 32; j += 8)
        vT[((size_t)b*EE + e0 + y + j) * TT + s0 + x] = t[x][y + j];
}

// ---------------- embed ------------------------------------------------------
__global__ void embed_kernel(const int* __restrict__ idx,
                             const float* __restrict__ tok,
                             const float* __restrict__ pos,
                             float* __restrict__ x) {
    int row = blockIdx.x;
    int t = row & (TT - 1);
    int token = idx[row];
    const float4* tp = (const float4*)(tok + (size_t)token * EE);
    const float4* pp = (const float4*)(pos + (size_t)t * EE);
    float4* xp = (float4*)(x + (size_t)row * EE);
    int c = threadIdx.x;
    float4 a = tp[c], b = pp[c];
    xp[c] = make_float4(a.x + b.x, a.y + b.y, a.z + b.z, a.w + b.w);
}

// ---------------- layernorm -> packed output (bf16 or fp16) ------------------
template <bool F16>
__global__ void ln_kernel(const float* __restrict__ x, uint32_t* __restrict__ out,
                          const float* __restrict__ g, const float* __restrict__ b) {
    int row = blockIdx.x;
    int tid = threadIdx.x;
    const float4* xp = (const float4*)(x + (size_t)row * EE);
    float4 v = xp[tid];
    float s = v.x + v.y + v.z + v.w;
    __shared__ float red[4];
    for (int o = 16; o; o >>= 1) s += __shfl_xor_sync(~0u, s, o);
    if ((tid & 31) == 0) red[tid >> 5] = s;
    __syncthreads();
    float mean = (red[0] + red[1] + red[2] + red[3]) / (float)EE;
    float dx = v.x - mean, dy = v.y - mean, dz = v.z - mean, dw = v.w - mean;
    float ss = dx*dx + dy*dy + dz*dz + dw*dw;
    __syncthreads();
    for (int o = 16; o; o >>= 1) ss += __shfl_xor_sync(~0u, ss, o);
    if ((tid & 31) == 0) red[tid >> 5] = ss;
    __syncthreads();
    float var = (red[0] + red[1] + red[2] + red[3]) / (float)EE;
    float inv = 1.0f / sqrtf(var + 1e-5f);
    const float4* gp = (const float4*)g;
    const float4* bp = (const float4*)b;
    float4 gg = gp[tid], bb = bp[tid];
    float o0 = dx*inv*gg.x + bb.x, o1 = dy*inv*gg.y + bb.y;
    float o2 = dz*inv*gg.z + bb.z, o3 = dw*inv*gg.w + bb.w;
    uint2 p01 = F16 ? packpair16(o0, o1) : packpair(o0, o1);
    uint2 p23 = F16 ? packpair16(o2, o3) : packpair(o2, o3);
    uint4* op = (uint4*)(out + (size_t)row * EE);
    op[tid] = make_uint4(p01.x, p01.y, p23.x, p23.y);
}

// ---------------- causal softmax row -> writes attn map into d_out ----------
__global__ void softmax_kernel(const float* __restrict__ S, float* __restrict__ out) {
    int row = blockIdx.x;
    int t = row & (TT - 1);
    const float* sp = S + (size_t)row * TT;
    float* op = out + (size_t)row * TT;
    int tid = threadIdx.x;
    float vals[4];
    float m = -1e30f;
    #pragma unroll
    for (int i = 0; i < 4; i++) {
        int s = tid + i * 256;
        vals[i] = (s <= t) ? sp[s] : -1e30f;
        m = fmaxf(m, vals[i]);
    }
    __shared__ float red[8];
    for (int o = 16; o; o >>= 1) m = fmaxf(m, __shfl_xor_sync(~0u, m, o));
    if ((tid & 31) == 0) red[tid >> 5] = m;
    __syncthreads();
    m = red[0];
    #pragma unroll
    for (int i = 1; i < 8; i++) m = fmaxf(m, red[i]);
    float e[4];
    float ssum = 0.0f;
    #pragma unroll
    for (int i = 0; i < 4; i++) {
        int s = tid + i * 256;
        e[i] = (s <= t) ? expf(vals[i] - m) : 0.0f;
        ssum += e[i];
    }
    __syncthreads();
    for (int o = 16; o; o >>= 1) ssum += __shfl_xor_sync(~0u, ssum, o);
    if ((tid & 31) == 0) red[tid >> 5] = ssum;
    __syncthreads();
    float tot = 0.0f;
    #pragma unroll
    for (int i = 0; i < 8; i++) tot += red[i];
    float inv = 1.0f / tot;
    #pragma unroll
    for (int i = 0; i < 4; i++) {
        int s = tid + i * 256;
        op[s] = e[i] * inv;
    }
}

// ---------------- host orchestration ----------------------------------------
extern "C" void kernel_launch(void* const* d_in, const int* in_sizes, int n_in,
                              void* d_out, int out_size) {
    (void)in_sizes; (void)n_in; (void)out_size;
    const int*   idx     = (const int*)  d_in[0];
    const float* tok_emb = (const float*)d_in[1];
    const float* pos_emb = (const float*)d_in[2];
    const float* ln1_g   = (const float*)d_in[3];
    const float* ln1_b   = (const float*)d_in[4];
    const float* Wq      = (const float*)d_in[5];
    const float* Wk      = (const float*)d_in[6];
    const float* Wv      = (const float*)d_in[7];
    const float* Wo      = (const float*)d_in[8];
    const float* bo      = (const float*)d_in[9];
    const float* ln2_g   = (const float*)d_in[10];
    const float* ln2_b   = (const float*)d_in[11];
    const float* W1      = (const float*)d_in[12];
    const float* b1      = (const float*)d_in[13];
    const float* W2      = (const float*)d_in[14];
    const float* b2      = (const float*)d_in[15];
    const float* lnf_g   = (const float*)d_in[16];
    const float* lnf_b   = (const float*)d_in[17];
    const float* Wlm     = (const float*)d_in[18];

    float* out    = (float*)d_out;
    float* logits = out;
    float* attn   = out + LOGITS_N;

    float *gx, *gS, *gb1p;
    uint32_t *gh, *gqkv, *gy, *gu, *gvT, *gWT, *gW1Tp, *gW2Tp;
    __half *gWlm16;
    cudaGetSymbolAddress((void**)&gx, d_x);
    cudaGetSymbolAddress((void**)&gh, d_h);
    cudaGetSymbolAddress((void**)&gqkv, d_qkv);
    cudaGetSymbolAddress((void**)&gy, d_y);
    cudaGetSymbolAddress((void**)&gu, d_u);
    cudaGetSymbolAddress((void**)&gS, d_S);
    cudaGetSymbolAddress((void**)&gvT, d_vT);
    cudaGetSymbolAddress((void**)&gWlm16, d_Wlm16);
    cudaGetSymbolAddress((void**)&gWT, d_WT);
    cudaGetSymbolAddress((void**)&gW1Tp, d_W1Tp);
    cudaGetSymbolAddress((void**)&gW2Tp, d_W2Tp);
    cudaGetSymbolAddress((void**)&gb1p, d_b1p);

    cudaFuncSetAttribute(mma_gemm<false,false,false,true>,
                         cudaFuncAttributeMaxDynamicSharedMemorySize, GEMM_SMEM);
    cudaFuncSetAttribute(mma_gemm<true,true,false,false>,
                         cudaFuncAttributeMaxDynamicSharedMemorySize, GEMM_SMEM);
    cudaFuncSetAttribute(mma_gemm<true,false,true,true>,
                         cudaFuncAttributeMaxDynamicSharedMemorySize, GEMM_SMEM);
    cudaFuncSetAttribute(qk_mma, cudaFuncAttributeMaxDynamicSharedMemorySize, GEMM_SMEM);
    cudaFuncSetAttribute(av_mma, cudaFuncAttributeMaxDynamicSharedMemorySize, AV_SMEM);
    cudaFuncSetAttribute(lm_gemm, cudaFuncAttributeMaxDynamicSharedMemorySize, LM_SMEM);

    // one merged weight-prep launch
    prep_kernel<<<PREP_BLOCKS, dim3(32, 8)>>>(Wq, Wk, Wv, Wo, W1, b1, W2, Wlm,
                                              gWT, gW1Tp, gW2Tp, gb1p, gWlm16);

    embed_kernel<<<BT, 128>>>(idx, tok_emb, pos_emb, gx);

    for (int l = 0; l < LL; l++) {
        uint32_t* base = gWT + (size_t)l * 4 * EE * EE;
        const uint32_t* qkvT = base;
        const uint32_t* woT  = base + (size_t)1536*EE;
        float* attn_l = attn + (size_t)l * ATT_PER_L;

        ln_kernel<false><<<BT, 128>>>(gx, gh, ln1_g + l*EE, ln1_b + l*EE);

        // fused QKV (packed in, packed out)
        mma_gemm<false,false,false,true><<<dim3(QKVS/128, BT/128), 256, GEMM_SMEM>>>(
            gh, qkvT, nullptr, nullptr, (float*)gqkv, BT, QKVS, EE);

        qk_mma<<<dim3(8, 8, BB*HH), 256, GEMM_SMEM>>>(gqkv, gS);
        softmax_kernel<<<BHT, 256>>>(gS, attn_l);
        vtrans_kernel<<<dim3(TT/32, EE/32, BB), dim3(32, 8)>>>(gqkv, gvT);
        av_mma<<<dim3(8, 1, BB*HH), 256, AV_SMEM>>>(attn_l, gvT, gy);

        // x = x + y @ Wo + bo
        mma_gemm<true,true,false,false><<<dim3(EE/128, BT/128), 256, GEMM_SMEM>>>(
            gy, woT, bo + l*EE, gx, gx, BT, EE, EE);

        ln_kernel<false><<<BT, 128>>>(gx, gh, ln2_g + l*EE, ln2_b + l*EE);

        // u = relu(h @ W1 + b1)
        mma_gemm<true,false,true,true><<<dim3(HIDP/128, BT/128), 256, GEMM_SMEM>>>(
            gh, gW1Tp + (size_t)l*HIDP*EE, gb1p + l*HIDP, nullptr, (float*)gu, BT, HIDP, EE);
        // x = x + u @ W2 + b2
        mma_gemm<true,true,false,false><<<dim3(EE/128, BT/128), 256, GEMM_SMEM>>>(
            gu, gW2Tp + (size_t)l*EE*HIDP, b2 + l*EE, gx, gx, BT, EE, HIDP);
    }

    // final LN packs fp16 pairs; logits uses hi plane only (1-term fp16)
    ln_kernel<true><<<BT, 128>>>(gx, gh, lnf_g, lnf_b);
    lm_gemm<<<dim3(BT/128, VV/128), 256, LM_SMEM>>>(gh, gWlm16, logits, BT, VV, EE);
}